// round 1
// baseline (speedup 1.0000x reference)
#include <cuda_runtime.h>

#define BB 4
#define NN 1024
#define DD 512
#define HH 8
#define DHD 64
#define TD (2*DD)          // 1024 (Q/K projected width)
#define MROWS (BB*NN)      // 4096

// Scratch for projected Q, K, V (static device globals: allocation-free).
__device__ float g_Q[(size_t)MROWS * TD];   // 16 MB
__device__ float g_K[(size_t)MROWS * TD];   // 16 MB
__device__ float g_V[(size_t)MROWS * DD];   // 8 MB

// ----------------------------------------------------------------------------
// Projection GEMM: C = A[M,512] @ W[512,N] + bias, row-major.
// 64x64 block tile, K-step 16, 256 threads, 4x4 microtile per thread.
// WHICH selects destination scratch buffer (0=Q, 1=K, 2=V).
// ----------------------------------------------------------------------------
template<int WHICH>
__global__ void proj_gemm(const float* __restrict__ A,
                          const float* __restrict__ W,
                          const float* __restrict__ bias,
                          int N) {
    const int K = DD;
    __shared__ float As[16][64];
    __shared__ float Bs[16][64];

    float* C = (WHICH == 0) ? g_Q : (WHICH == 1) ? g_K : g_V;

    int bx = blockIdx.x;           // N tile
    int by = blockIdx.y;           // M tile
    int tid = threadIdx.x;
    int tx = tid & 15;
    int ty = tid >> 4;

    float acc[4][4] = {};
    const float* Ab = A + (size_t)by * 64 * K;
    const float* Wb = W + (size_t)bx * 64;

    for (int k0 = 0; k0 < K; k0 += 16) {
        // A tile: 64 rows x 16 cols
        #pragma unroll
        for (int i = tid; i < 64 * 16; i += 256) {
            int r = i >> 4, c = i & 15;
            As[c][r] = Ab[(size_t)r * K + k0 + c];
        }
        // W tile: 16 rows x 64 cols (fully coalesced)
        #pragma unroll
        for (int i = tid; i < 16 * 64; i += 256) {
            int r = i >> 6, c = i & 63;
            Bs[r][c] = Wb[(size_t)(k0 + r) * N + c];
        }
        __syncthreads();
        #pragma unroll
        for (int kk = 0; kk < 16; kk++) {
            float a[4], b[4];
            #pragma unroll
            for (int i = 0; i < 4; i++) a[i] = As[kk][ty * 4 + i];
            #pragma unroll
            for (int j = 0; j < 4; j++) b[j] = Bs[kk][tx * 4 + j];
            #pragma unroll
            for (int i = 0; i < 4; i++)
                #pragma unroll
                for (int j = 0; j < 4; j++)
                    acc[i][j] += a[i] * b[j];
        }
        __syncthreads();
    }

    #pragma unroll
    for (int i = 0; i < 4; i++) {
        int row = by * 64 + ty * 4 + i;
        #pragma unroll
        for (int j = 0; j < 4; j++) {
            int col = bx * 64 + tx * 4 + j;
            C[(size_t)row * N + col] = acc[i][j] + bias[col];
        }
    }
}

// ----------------------------------------------------------------------------
// Differential attention, flash-style over k-tiles, dual online softmax.
// Block = (q_tile of 64 rows, head h, batch b). 256 threads, 4x4 microtiles.
// out[q,d] = sum_k softmax1(q1 k1^T)[q,k] v[k,d] - 0.5 * softmax2(...) v
// ----------------------------------------------------------------------------
#define SP 65   // padded smem stride (bank-conflict-free column access)

__global__ void diff_attn(float* __restrict__ out) {
    extern __shared__ float sm[];
    float* Q1s = sm;                  // [64][SP] layout [d][q]
    float* Q2s = Q1s + 64 * SP;
    float* K1s = Q2s + 64 * SP;       // [d][k]
    float* K2s = K1s + 64 * SP;
    float* Vs  = K2s + 64 * SP;       // [k][d]
    float* S1s = Vs  + 64 * SP;       // [q][k] -> exp'd probs in place
    float* S2s = S1s + 64 * SP;
    float* m1  = S2s + 64 * SP;
    float* l1  = m1 + 64;
    float* m2  = l1 + 64;
    float* l2  = m2 + 64;
    float* al1 = l2 + 64;
    float* al2 = al1 + 64;

    int qt = blockIdx.x;
    int h  = blockIdx.y;
    int b  = blockIdx.z;
    int tid = threadIdx.x;
    int tx = tid & 15;
    int ty = tid >> 4;
    const float scale = 0.125f;       // 1/sqrt(64)

    const size_t qrow0 = (size_t)b * NN + (size_t)qt * 64;

    // Load Q tiles once (pre-scaled)
    for (int i = tid; i < 64 * 64; i += 256) {
        int q = i >> 6, d = i & 63;
        size_t base = (qrow0 + q) * TD + (size_t)h * 128;
        Q1s[d * SP + q] = g_Q[base + d] * scale;
        Q2s[d * SP + q] = g_Q[base + 64 + d] * scale;
    }
    if (tid < 64) {
        m1[tid] = -1e30f; l1[tid] = 0.f;
        m2[tid] = -1e30f; l2[tid] = 0.f;
    }
    float acc1[4][4] = {}, acc2[4][4] = {};
    __syncthreads();

    for (int kt = 0; kt < NN / 64; kt++) {
        size_t krow0 = (size_t)b * NN + (size_t)kt * 64;
        for (int i = tid; i < 64 * 64; i += 256) {
            int k = i >> 6, d = i & 63;
            size_t kb = (krow0 + k) * TD + (size_t)h * 128;
            K1s[d * SP + k] = g_K[kb + d];
            K2s[d * SP + k] = g_K[kb + 64 + d];
            Vs[k * SP + d]  = g_V[(krow0 + k) * DD + (size_t)h * 64 + d];
        }
        __syncthreads();

        // S = Q K^T (both heads' halves at once)
        float s1[4][4] = {}, s2[4][4] = {};
        #pragma unroll
        for (int kk = 0; kk < 64; kk++) {
            float a1[4], b1[4], a2[4], b2[4];
            #pragma unroll
            for (int i = 0; i < 4; i++) {
                a1[i] = Q1s[kk * SP + ty * 4 + i];
                a2[i] = Q2s[kk * SP + ty * 4 + i];
            }
            #pragma unroll
            for (int j = 0; j < 4; j++) {
                b1[j] = K1s[kk * SP + tx * 4 + j];
                b2[j] = K2s[kk * SP + tx * 4 + j];
            }
            #pragma unroll
            for (int i = 0; i < 4; i++)
                #pragma unroll
                for (int j = 0; j < 4; j++) {
                    s1[i][j] += a1[i] * b1[j];
                    s2[i][j] += a2[i] * b2[j];
                }
        }
        #pragma unroll
        for (int i = 0; i < 4; i++)
            #pragma unroll
            for (int j = 0; j < 4; j++) {
                S1s[(ty * 4 + i) * SP + tx * 4 + j] = s1[i][j];
                S2s[(ty * 4 + i) * SP + tx * 4 + j] = s2[i][j];
            }
        __syncthreads();

        // Online softmax row update (threads 0..63 -> S1 rows, 64..127 -> S2)
        if (tid < 128) {
            int r = tid & 63;
            float* S  = (tid < 64) ? S1s : S2s;
            float* m  = (tid < 64) ? m1  : m2;
            float* l  = (tid < 64) ? l1  : l2;
            float* al = (tid < 64) ? al1 : al2;
            float tm = -1e30f;
            #pragma unroll
            for (int k = 0; k < 64; k++) tm = fmaxf(tm, S[r * SP + k]);
            float mn = fmaxf(m[r], tm);
            float a = __expf(m[r] - mn);
            float sum = 0.f;
            #pragma unroll
            for (int k = 0; k < 64; k++) {
                float p = __expf(S[r * SP + k] - mn);
                S[r * SP + k] = p;
                sum += p;
            }
            l[r] = l[r] * a + sum;
            m[r] = mn;
            al[r] = a;
        }
        __syncthreads();

        // Rescale accumulators, then P @ V
        float a1r[4], a2r[4];
        #pragma unroll
        for (int i = 0; i < 4; i++) {
            a1r[i] = al1[ty * 4 + i];
            a2r[i] = al2[ty * 4 + i];
        }
        #pragma unroll
        for (int i = 0; i < 4; i++)
            #pragma unroll
            for (int j = 0; j < 4; j++) {
                acc1[i][j] *= a1r[i];
                acc2[i][j] *= a2r[i];
            }
        #pragma unroll
        for (int kk = 0; kk < 64; kk++) {
            float p1[4], p2[4], v[4];
            #pragma unroll
            for (int i = 0; i < 4; i++) {
                p1[i] = S1s[(ty * 4 + i) * SP + kk];
                p2[i] = S2s[(ty * 4 + i) * SP + kk];
            }
            #pragma unroll
            for (int j = 0; j < 4; j++) v[j] = Vs[kk * SP + tx * 4 + j];
            #pragma unroll
            for (int i = 0; i < 4; i++)
                #pragma unroll
                for (int j = 0; j < 4; j++) {
                    acc1[i][j] += p1[i] * v[j];
                    acc2[i][j] += p2[i] * v[j];
                }
        }
        __syncthreads();
    }

    // Final normalize + differential combine; write out[b,n,h*64+d]
    #pragma unroll
    for (int i = 0; i < 4; i++) {
        int r = ty * 4 + i;
        float inv1 = 1.f / l1[r];
        float inv2 = 0.5f / l2[r];
        size_t rowbase = (qrow0 + r) * DD + (size_t)h * 64;
        #pragma unroll
        for (int j = 0; j < 4; j++) {
            out[rowbase + tx * 4 + j] = acc1[i][j] * inv1 - acc2[i][j] * inv2;
        }
    }
}

static const size_t ATTN_SMEM = (7 * 64 * SP + 6 * 64) * sizeof(float);  // ~118 KB

extern "C" void kernel_launch(void* const* d_in, const int* in_sizes, int n_in,
                              void* d_out, int out_size) {
    (void)in_sizes; (void)n_in; (void)out_size;
    const float* x  = (const float*)d_in[0];
    const float* Wq = (const float*)d_in[1];
    const float* bq = (const float*)d_in[2];
    const float* Wk = (const float*)d_in[3];
    const float* bk = (const float*)d_in[4];
    const float* Wv = (const float*)d_in[5];
    const float* bv = (const float*)d_in[6];
    float* out = (float*)d_out;

    cudaFuncSetAttribute(diff_attn, cudaFuncAttributeMaxDynamicSharedMemorySize,
                         (int)ATTN_SMEM);

    dim3 blk(256);
    proj_gemm<0><<<dim3(TD / 64, MROWS / 64), blk>>>(x, Wq, bq, TD);
    proj_gemm<1><<<dim3(TD / 64, MROWS / 64), blk>>>(x, Wk, bk, TD);
    proj_gemm<2><<<dim3(DD / 64, MROWS / 64), blk>>>(x, Wv, bv, DD);
    diff_attn<<<dim3(NN / 64, HH, BB), blk, ATTN_SMEM>>>(out);
}

// round 2
// speedup vs baseline: 2.0639x; 2.0639x over previous
#include <cuda_runtime.h>
#include <cstdint>

#define BB 4
#define NN 1024
#define DD 512
#define HH 8
#define TD (2*DD)          // 1024
#define MROWS (BB*NN)      // 4096

// Scratch for projected Q, K, V
__device__ float g_Q[(size_t)MROWS * TD];
__device__ float g_K[(size_t)MROWS * TD];
__device__ float g_V[(size_t)MROWS * DD];

__device__ __forceinline__ float to_tf32(float x) {
    unsigned u;
    asm("cvt.rna.tf32.f32 %0, %1;" : "=r"(u) : "f"(x));
    return __uint_as_float(u);
}

// C += A(16x8, row) @ B(8x8, col)  tf32
__device__ __forceinline__ void mma8(float* c, const uint32_t* a, const uint32_t* b) {
    asm volatile(
        "mma.sync.aligned.m16n8k8.row.col.f32.tf32.tf32.f32 "
        "{%0,%1,%2,%3},{%4,%5,%6,%7},{%8,%9},{%0,%1,%2,%3};"
        : "+f"(c[0]), "+f"(c[1]), "+f"(c[2]), "+f"(c[3])
        : "r"(a[0]), "r"(a[1]), "r"(a[2]), "r"(a[3]), "r"(b[0]), "r"(b[1]));
}

// ----------------------------------------------------------------------------
// Projection GEMM (tf32 mma): C[M,N] = A[M,512] @ W[512,N] + bias
// Block tile 128x64, 8 warps (4x2), warp tile 32x32, K-chunk 32.
// ----------------------------------------------------------------------------
#define SA 36   // A smem stride (rows x k): bank = 4*row + k  -> conflict-free frags
#define SB 72   // B smem stride (k x n):    bank = 8*k + n    -> conflict-free frags

template<int WHICH>
__global__ __launch_bounds__(256) void proj_mma(const float* __restrict__ A,
                                                const float* __restrict__ W,
                                                const float* __restrict__ bias,
                                                int N) {
    __shared__ float As[128 * SA];
    __shared__ float Bs[32 * SB];
    float* C = (WHICH == 0) ? g_Q : (WHICH == 1) ? g_K : g_V;

    const int tid = threadIdx.x, lane = tid & 31, w = tid >> 5;
    const int wm = w >> 1, wn = w & 1;          // 4x2 warp grid
    const int g = lane >> 2, t4 = lane & 3;

    float acc[2][4][4] = {};
    const float* Ab = A + (size_t)blockIdx.y * 128 * 512;
    const float* Wb = W + (size_t)blockIdx.x * 64;

    for (int k0 = 0; k0 < 512; k0 += 32) {
        #pragma unroll
        for (int i = tid; i < 128 * 32; i += 256) {
            int r = i >> 5, c = i & 31;
            As[r * SA + c] = to_tf32(Ab[(size_t)r * 512 + k0 + c]);
        }
        #pragma unroll
        for (int i = tid; i < 32 * 64; i += 256) {
            int r = i >> 6, c = i & 63;
            Bs[r * SB + c] = to_tf32(Wb[(size_t)(k0 + r) * N + c]);
        }
        __syncthreads();

        #pragma unroll
        for (int ks = 0; ks < 4; ks++) {
            const int kb = ks * 8;
            uint32_t a[2][4], bf[4][2];
            #pragma unroll
            for (int mt = 0; mt < 2; mt++) {
                int row = wm * 32 + mt * 16 + g;
                a[mt][0] = __float_as_uint(As[row * SA + kb + t4]);
                a[mt][1] = __float_as_uint(As[(row + 8) * SA + kb + t4]);
                a[mt][2] = __float_as_uint(As[row * SA + kb + t4 + 4]);
                a[mt][3] = __float_as_uint(As[(row + 8) * SA + kb + t4 + 4]);
            }
            #pragma unroll
            for (int nt = 0; nt < 4; nt++) {
                int col = wn * 32 + nt * 8 + g;
                bf[nt][0] = __float_as_uint(Bs[(kb + t4) * SB + col]);
                bf[nt][1] = __float_as_uint(Bs[(kb + t4 + 4) * SB + col]);
            }
            #pragma unroll
            for (int mt = 0; mt < 2; mt++)
                #pragma unroll
                for (int nt = 0; nt < 4; nt++)
                    mma8(acc[mt][nt], a[mt], bf[nt]);
        }
        __syncthreads();
    }

    // Epilogue
    #pragma unroll
    for (int mt = 0; mt < 2; mt++) {
        int row0 = blockIdx.y * 128 + wm * 32 + mt * 16 + g;
        #pragma unroll
        for (int nt = 0; nt < 4; nt++) {
            int col = blockIdx.x * 64 + wn * 32 + nt * 8 + 2 * t4;
            C[(size_t)row0 * N + col]       = acc[mt][nt][0] + bias[col];
            C[(size_t)row0 * N + col + 1]   = acc[mt][nt][1] + bias[col + 1];
            C[(size_t)(row0 + 8) * N + col]     = acc[mt][nt][2] + bias[col];
            C[(size_t)(row0 + 8) * N + col + 1] = acc[mt][nt][3] + bias[col + 1];
        }
    }
}

// ----------------------------------------------------------------------------
// Differential attention, tf32 mma, dual online softmax.
// Warps 0-3: path1 (q1k1, a1@v). Warps 4-7: path2. 32x32 warp tiles (2x2 grid).
// ----------------------------------------------------------------------------
#define SQ 68   // [row][d] stride: frag bank = 4*row + t4 -> conflict-free
#define SV 72   // V [key][d] stride: frag bank = 8*k + d  -> conflict-free

__global__ __launch_bounds__(256) void diff_attn(float* __restrict__ out) {
    extern __shared__ float sm[];
    float* Q1s = sm;                   // [q][d]
    float* Q2s = Q1s + 64 * SQ;
    float* K1s = Q2s + 64 * SQ;        // [key][d]
    float* K2s = K1s + 64 * SQ;
    float* S1s = K2s + 64 * SQ;        // [q][k]
    float* S2s = S1s + 64 * SQ;
    float* Vs  = S2s + 64 * SQ;        // [key][d]
    float* m1  = Vs + 64 * SV;
    float* l1  = m1 + 64;
    float* m2  = l1 + 64;
    float* l2  = m2 + 64;
    float* al1 = l2 + 64;
    float* al2 = al1 + 64;

    const int qt = blockIdx.x, h = blockIdx.y, b = blockIdx.z;
    const int tid = threadIdx.x, lane = tid & 31, w = tid >> 5;
    const int ww = w & 3, wm = ww >> 1, wn = ww & 1;
    const bool mat2 = (w >= 4);
    const int g = lane >> 2, t4 = lane & 3;
    const size_t qrow0 = (size_t)b * NN + (size_t)qt * 64;

    // Load Q, pre-scaled, tf32-rounded
    for (int i = tid; i < 64 * 64; i += 256) {
        int q = i >> 6, d = i & 63;
        size_t base = (qrow0 + q) * TD + (size_t)h * 128;
        Q1s[q * SQ + d] = to_tf32(g_Q[base + d] * 0.125f);
        Q2s[q * SQ + d] = to_tf32(g_Q[base + 64 + d] * 0.125f);
    }
    if (tid < 64) {
        m1[tid] = -1e30f; l1[tid] = 0.f;
        m2[tid] = -1e30f; l2[tid] = 0.f;
    }
    float acco[2][4][4] = {};   // persistent PV accumulator (32x32 warp tile)
    __syncthreads();

    float* Qs = mat2 ? Q2s : Q1s;
    float* Ks = mat2 ? K2s : K1s;
    float* Ss = mat2 ? S2s : S1s;
    float* alp = mat2 ? al2 : al1;

    for (int kt = 0; kt < NN / 64; kt++) {
        size_t krow0 = (size_t)b * NN + (size_t)kt * 64;
        for (int i = tid; i < 64 * 64; i += 256) {
            int k = i >> 6, d = i & 63;
            size_t kb = (krow0 + k) * TD + (size_t)h * 128;
            K1s[k * SQ + d] = to_tf32(g_K[kb + d]);
            K2s[k * SQ + d] = to_tf32(g_K[kb + 64 + d]);
            Vs[k * SV + d]  = to_tf32(g_V[(krow0 + k) * DD + (size_t)h * 64 + d]);
        }
        __syncthreads();

        // ---- S = Q @ K^T (warp computes its 32x32 tile of its matrix) ----
        float accs[2][4][4] = {};
        #pragma unroll
        for (int ks = 0; ks < 8; ks++) {
            const int kb = ks * 8;
            uint32_t a[2][4], bf[4][2];
            #pragma unroll
            for (int mt = 0; mt < 2; mt++) {
                int row = wm * 32 + mt * 16 + g;
                a[mt][0] = __float_as_uint(Qs[row * SQ + kb + t4]);
                a[mt][1] = __float_as_uint(Qs[(row + 8) * SQ + kb + t4]);
                a[mt][2] = __float_as_uint(Qs[row * SQ + kb + t4 + 4]);
                a[mt][3] = __float_as_uint(Qs[(row + 8) * SQ + kb + t4 + 4]);
            }
            #pragma unroll
            for (int nt = 0; nt < 4; nt++) {
                int col = wn * 32 + nt * 8 + g;
                bf[nt][0] = __float_as_uint(Ks[col * SQ + kb + t4]);
                bf[nt][1] = __float_as_uint(Ks[col * SQ + kb + t4 + 4]);
            }
            #pragma unroll
            for (int mt = 0; mt < 2; mt++)
                #pragma unroll
                for (int nt = 0; nt < 4; nt++)
                    mma8(accs[mt][nt], a[mt], bf[nt]);
        }
        #pragma unroll
        for (int mt = 0; mt < 2; mt++)
            #pragma unroll
            for (int nt = 0; nt < 4; nt++) {
                int row = wm * 32 + mt * 16 + g, col = wn * 32 + nt * 8 + 2 * t4;
                Ss[row * SQ + col]           = accs[mt][nt][0];
                Ss[row * SQ + col + 1]       = accs[mt][nt][1];
                Ss[(row + 8) * SQ + col]     = accs[mt][nt][2];
                Ss[(row + 8) * SQ + col + 1] = accs[mt][nt][3];
            }
        __syncthreads();

        // ---- online softmax (1 thread / row, skewed walk -> conflict-free) ----
        if (tid < 128) {
            int r = tid & 63;
            float* S  = (tid < 64) ? S1s : S2s;
            float* m  = (tid < 64) ? m1  : m2;
            float* l  = (tid < 64) ? l1  : l2;
            float* al = (tid < 64) ? al1 : al2;
            float tm = -1e30f;
            #pragma unroll
            for (int kk = 0; kk < 64; kk++) {
                int k = (kk + r) & 63;
                tm = fmaxf(tm, S[r * SQ + k]);
            }
            float mn = fmaxf(m[r], tm);
            float a = __expf(m[r] - mn);
            float sum = 0.f;
            #pragma unroll
            for (int kk = 0; kk < 64; kk++) {
                int k = (kk + r) & 63;
                float p = __expf(S[r * SQ + k] - mn);
                S[r * SQ + k] = to_tf32(p);
                sum += p;
            }
            l[r] = l[r] * a + sum;
            m[r] = mn;
            al[r] = a;
        }
        __syncthreads();

        // ---- rescale accumulator, then acc += P @ V ----
        #pragma unroll
        for (int mt = 0; mt < 2; mt++) {
            int row = wm * 32 + mt * 16 + g;
            float a0 = alp[row], a8 = alp[row + 8];
            #pragma unroll
            for (int nt = 0; nt < 4; nt++) {
                acco[mt][nt][0] *= a0; acco[mt][nt][1] *= a0;
                acco[mt][nt][2] *= a8; acco[mt][nt][3] *= a8;
            }
        }
        #pragma unroll
        for (int ks = 0; ks < 8; ks++) {
            const int kb = ks * 8;
            uint32_t a[2][4], bf[4][2];
            #pragma unroll
            for (int mt = 0; mt < 2; mt++) {
                int row = wm * 32 + mt * 16 + g;
                a[mt][0] = __float_as_uint(Ss[row * SQ + kb + t4]);
                a[mt][1] = __float_as_uint(Ss[(row + 8) * SQ + kb + t4]);
                a[mt][2] = __float_as_uint(Ss[row * SQ + kb + t4 + 4]);
                a[mt][3] = __float_as_uint(Ss[(row + 8) * SQ + kb + t4 + 4]);
            }
            #pragma unroll
            for (int nt = 0; nt < 4; nt++) {
                int col = wn * 32 + nt * 8 + g;
                bf[nt][0] = __float_as_uint(Vs[(kb + t4) * SV + col]);
                bf[nt][1] = __float_as_uint(Vs[(kb + t4 + 4) * SV + col]);
            }
            #pragma unroll
            for (int mt = 0; mt < 2; mt++)
                #pragma unroll
                for (int nt = 0; nt < 4; nt++)
                    mma8(acco[mt][nt], a[mt], bf[nt]);
        }
        __syncthreads();
    }

    // ---- finalize: write normalized per-path outputs to S buffers, combine ----
    {
        float* L = mat2 ? l2 : l1;
        const float lam = mat2 ? 0.5f : 1.0f;
        #pragma unroll
        for (int mt = 0; mt < 2; mt++) {
            int row = wm * 32 + mt * 16 + g;
            float inv0 = lam / L[row];
            float inv8 = lam / L[row + 8];
            #pragma unroll
            for (int nt = 0; nt < 4; nt++) {
                int col = wn * 32 + nt * 8 + 2 * t4;
                Ss[row * SQ + col]           = acco[mt][nt][0] * inv0;
                Ss[row * SQ + col + 1]       = acco[mt][nt][1] * inv0;
                Ss[(row + 8) * SQ + col]     = acco[mt][nt][2] * inv8;
                Ss[(row + 8) * SQ + col + 1] = acco[mt][nt][3] * inv8;
            }
        }
    }
    __syncthreads();
    for (int i = tid; i < 64 * 64; i += 256) {
        int q = i >> 6, d = i & 63;
        out[(qrow0 + q) * DD + (size_t)h * 64 + d] = S1s[q * SQ + d] - S2s[q * SQ + d];
    }
}

static const size_t ATTN_SMEM = (6 * 64 * SQ + 64 * SV + 6 * 64) * sizeof(float); // ~124 KB

extern "C" void kernel_launch(void* const* d_in, const int* in_sizes, int n_in,
                              void* d_out, int out_size) {
    (void)in_sizes; (void)n_in; (void)out_size;
    const float* x  = (const float*)d_in[0];
    const float* Wq = (const float*)d_in[1];
    const float* bq = (const float*)d_in[2];
    const float* Wk = (const float*)d_in[3];
    const float* bk = (const float*)d_in[4];
    const float* Wv = (const float*)d_in[5];
    const float* bv = (const float*)d_in[6];
    float* out = (float*)d_out;

    cudaFuncSetAttribute(diff_attn, cudaFuncAttributeMaxDynamicSharedMemorySize,
                         (int)ATTN_SMEM);

    dim3 blk(256);
    proj_mma<0><<<dim3(TD / 64, MROWS / 128), blk>>>(x, Wq, bq, TD);
    proj_mma<1><<<dim3(TD / 64, MROWS / 128), blk>>>(x, Wk, bk, TD);
    proj_mma<2><<<dim3(DD / 64, MROWS / 128), blk>>>(x, Wv, bv, DD);
    diff_attn<<<dim3(NN / 64, HH, BB), blk, ATTN_SMEM>>>(out);
}

// round 3
// speedup vs baseline: 3.7997x; 1.8410x over previous
#include <cuda_runtime.h>
#include <cstdint>

#define BB 4
#define NN 1024
#define DD 512
#define HH 8
#define TD (2*DD)          // 1024
#define MROWS (BB*NN)      // 4096

// Scratch for projected Q, K, V (tf32-pre-rounded by projection epilogues)
__device__ float g_Q[(size_t)MROWS * TD];
__device__ float g_K[(size_t)MROWS * TD];
__device__ float g_V[(size_t)MROWS * DD];

__device__ __forceinline__ float to_tf32(float x) {
    unsigned u;
    asm("cvt.rna.tf32.f32 %0, %1;" : "=r"(u) : "f"(x));
    return __uint_as_float(u);
}

// C += A(16x8, row) @ B(8x8, col)  tf32
__device__ __forceinline__ void mma8(float* c, const uint32_t* a, const uint32_t* b) {
    asm volatile(
        "mma.sync.aligned.m16n8k8.row.col.f32.tf32.tf32.f32 "
        "{%0,%1,%2,%3},{%4,%5,%6,%7},{%8,%9},{%0,%1,%2,%3};"
        : "+f"(c[0]), "+f"(c[1]), "+f"(c[2]), "+f"(c[3])
        : "r"(a[0]), "r"(a[1]), "r"(a[2]), "r"(a[3]), "r"(b[0]), "r"(b[1]));
}

// ----------------------------------------------------------------------------
// Projection GEMM (tf32 mma): C[M,N] = tf32_round(A[M,512] @ W[512,N] + bias)
// ----------------------------------------------------------------------------
#define SA 36
#define SB 72

template<int WHICH>
__global__ __launch_bounds__(256) void proj_mma(const float* __restrict__ A,
                                                const float* __restrict__ W,
                                                const float* __restrict__ bias,
                                                int N) {
    __shared__ float As[128 * SA];
    __shared__ float Bs[32 * SB];
    float* C = (WHICH == 0) ? g_Q : (WHICH == 1) ? g_K : g_V;

    const int tid = threadIdx.x, lane = tid & 31, w = tid >> 5;
    const int wm = w >> 1, wn = w & 1;
    const int g = lane >> 2, t4 = lane & 3;

    float acc[2][4][4] = {};
    const float* Ab = A + (size_t)blockIdx.y * 128 * 512;
    const float* Wb = W + (size_t)blockIdx.x * 64;

    for (int k0 = 0; k0 < 512; k0 += 32) {
        #pragma unroll
        for (int i = tid; i < 128 * 32; i += 256) {
            int r = i >> 5, c = i & 31;
            As[r * SA + c] = to_tf32(Ab[(size_t)r * 512 + k0 + c]);
        }
        #pragma unroll
        for (int i = tid; i < 32 * 64; i += 256) {
            int r = i >> 6, c = i & 63;
            Bs[r * SB + c] = to_tf32(Wb[(size_t)(k0 + r) * N + c]);
        }
        __syncthreads();

        #pragma unroll
        for (int ks = 0; ks < 4; ks++) {
            const int kb = ks * 8;
            uint32_t a[2][4], bf[4][2];
            #pragma unroll
            for (int mt = 0; mt < 2; mt++) {
                int row = wm * 32 + mt * 16 + g;
                a[mt][0] = __float_as_uint(As[row * SA + kb + t4]);
                a[mt][1] = __float_as_uint(As[(row + 8) * SA + kb + t4]);
                a[mt][2] = __float_as_uint(As[row * SA + kb + t4 + 4]);
                a[mt][3] = __float_as_uint(As[(row + 8) * SA + kb + t4 + 4]);
            }
            #pragma unroll
            for (int nt = 0; nt < 4; nt++) {
                int col = wn * 32 + nt * 8 + g;
                bf[nt][0] = __float_as_uint(Bs[(kb + t4) * SB + col]);
                bf[nt][1] = __float_as_uint(Bs[(kb + t4 + 4) * SB + col]);
            }
            #pragma unroll
            for (int mt = 0; mt < 2; mt++)
                #pragma unroll
                for (int nt = 0; nt < 4; nt++)
                    mma8(acc[mt][nt], a[mt], bf[nt]);
        }
        __syncthreads();
    }

    #pragma unroll
    for (int mt = 0; mt < 2; mt++) {
        int row0 = blockIdx.y * 128 + wm * 32 + mt * 16 + g;
        #pragma unroll
        for (int nt = 0; nt < 4; nt++) {
            int col = blockIdx.x * 64 + wn * 32 + nt * 8 + 2 * t4;
            C[(size_t)row0 * N + col]           = to_tf32(acc[mt][nt][0] + bias[col]);
            C[(size_t)row0 * N + col + 1]       = to_tf32(acc[mt][nt][1] + bias[col + 1]);
            C[(size_t)(row0 + 8) * N + col]     = to_tf32(acc[mt][nt][2] + bias[col]);
            C[(size_t)(row0 + 8) * N + col + 1] = to_tf32(acc[mt][nt][3] + bias[col + 1]);
        }
    }
}

// ----------------------------------------------------------------------------
// Differential attention: warp = 16 q-rows x full 64-key tile of ONE path.
// Warps 0-3 path1 rows 0..63, warps 4-7 path2. Softmax + stats in registers.
// ----------------------------------------------------------------------------
#define SP 68   // [row][col] stride (K, P buffers): conflict-free frag access
#define SV 72   // V [key][d] stride: conflict-free B-frag access

__global__ __launch_bounds__(256, 2) void diff_attn(float* __restrict__ out) {
    extern __shared__ float sm[];
    float* K1s = sm;                   // [key][d]
    float* K2s = K1s + 64 * SP;
    float* Vs  = K2s + 64 * SP;        // [key][d]
    float* P1s = Vs  + 64 * SV;        // [q][k] probs / staging / output
    float* P2s = P1s + 64 * SP;

    const int qt = blockIdx.x, h = blockIdx.y, b = blockIdx.z;
    const int tid = threadIdx.x, lane = tid & 31, w = tid >> 5;
    const int wp = w & 3;              // row-block within path
    const int path = w >> 2;           // 0 or 1
    const int g = lane >> 2, t4 = lane & 3;
    const size_t qrow0 = (size_t)b * NN + (size_t)qt * 64;

    float* Ks = path ? K2s : K1s;
    float* Ps = path ? P2s : P1s;

    // ---- stage Q (both halves) into P buffers, then lift to A-fragments ----
    for (int i = tid; i < 2048; i += 256) {           // 2 paths x 64 rows x 16 f4
        int pi = i >> 10, rem = i & 1023, row = rem >> 4, c4 = rem & 15;
        const float4 v = *(const float4*)&g_Q[(qrow0 + row) * TD + (size_t)h * 128 + pi * 64 + c4 * 4];
        float* dst = (pi ? P2s : P1s) + row * SP + c4 * 4;
        *(float4*)dst = v;
    }
    __syncthreads();

    uint32_t qa[8][4];
    {
        const int row = wp * 16 + g;
        #pragma unroll
        for (int ks = 0; ks < 8; ks++) {
            const int kb = ks * 8;
            qa[ks][0] = __float_as_uint(Ps[row * SP + kb + t4] * 0.125f);
            qa[ks][1] = __float_as_uint(Ps[(row + 8) * SP + kb + t4] * 0.125f);
            qa[ks][2] = __float_as_uint(Ps[row * SP + kb + t4 + 4] * 0.125f);
            qa[ks][3] = __float_as_uint(Ps[(row + 8) * SP + kb + t4 + 4] * 0.125f);
        }
    }
    __syncthreads();

    float acco[8][4] = {};
    float m0 = -1e30f, m1 = -1e30f, l0 = 0.f, l1 = 0.f;

    for (int kt = 0; kt < NN / 64; kt++) {
        const size_t krow0 = (size_t)b * NN + (size_t)kt * 64;
        // ---- load K1,K2 (64 rows x 32 f4) and V (64 x 16 f4) ----
        for (int i = tid; i < 2048; i += 256) {
            int row = i >> 5, c4 = i & 31;
            const float4 v = *(const float4*)&g_K[(krow0 + row) * TD + (size_t)h * 128 + c4 * 4];
            float* dst = (c4 < 16 ? K1s + row * SP + c4 * 4
                                  : K2s + row * SP + (c4 - 16) * 4);
            *(float4*)dst = v;
        }
        for (int i = tid; i < 1024; i += 256) {
            int row = i >> 4, c4 = i & 15;
            const float4 v = *(const float4*)&g_V[(krow0 + row) * DD + (size_t)h * 64 + c4 * 4];
            *(float4*)&Vs[row * SV + c4 * 4] = v;
        }
        __syncthreads();

        // ---- S = Q @ K^T  (warp: 16 rows x 64 keys) ----
        float accs[8][4] = {};
        #pragma unroll
        for (int ks = 0; ks < 8; ks++) {
            const int kb = ks * 8;
            #pragma unroll
            for (int nt = 0; nt < 8; nt++) {
                uint32_t bf[2];
                const int col = nt * 8 + g;
                bf[0] = __float_as_uint(Ks[col * SP + kb + t4]);
                bf[1] = __float_as_uint(Ks[col * SP + kb + t4 + 4]);
                mma8(accs[nt], qa[ks], bf);
            }
        }

        // ---- online softmax in registers ----
        float tm0 = -1e30f, tm1 = -1e30f;
        #pragma unroll
        for (int nt = 0; nt < 8; nt++) {
            tm0 = fmaxf(tm0, fmaxf(accs[nt][0], accs[nt][1]));
            tm1 = fmaxf(tm1, fmaxf(accs[nt][2], accs[nt][3]));
        }
        tm0 = fmaxf(tm0, __shfl_xor_sync(0xffffffffu, tm0, 1));
        tm0 = fmaxf(tm0, __shfl_xor_sync(0xffffffffu, tm0, 2));
        tm1 = fmaxf(tm1, __shfl_xor_sync(0xffffffffu, tm1, 1));
        tm1 = fmaxf(tm1, __shfl_xor_sync(0xffffffffu, tm1, 2));
        const float mn0 = fmaxf(m0, tm0), mn1 = fmaxf(m1, tm1);
        const float al0 = __expf(m0 - mn0), al1 = __expf(m1 - mn1);
        float s0 = 0.f, s1 = 0.f;
        #pragma unroll
        for (int nt = 0; nt < 8; nt++) {
            accs[nt][0] = __expf(accs[nt][0] - mn0);
            accs[nt][1] = __expf(accs[nt][1] - mn0);
            accs[nt][2] = __expf(accs[nt][2] - mn1);
            accs[nt][3] = __expf(accs[nt][3] - mn1);
            s0 += accs[nt][0] + accs[nt][1];
            s1 += accs[nt][2] + accs[nt][3];
        }
        s0 += __shfl_xor_sync(0xffffffffu, s0, 1);
        s0 += __shfl_xor_sync(0xffffffffu, s0, 2);
        s1 += __shfl_xor_sync(0xffffffffu, s1, 1);
        s1 += __shfl_xor_sync(0xffffffffu, s1, 2);
        l0 = l0 * al0 + s0;  m0 = mn0;
        l1 = l1 * al1 + s1;  m1 = mn1;

        // ---- rescale output accumulator; store P (tf32) to smem ----
        {
            const int row = wp * 16 + g;
            #pragma unroll
            for (int nt = 0; nt < 8; nt++) {
                acco[nt][0] *= al0;  acco[nt][1] *= al0;
                acco[nt][2] *= al1;  acco[nt][3] *= al1;
                const int col = nt * 8 + 2 * t4;
                float2 p0 = make_float2(to_tf32(accs[nt][0]), to_tf32(accs[nt][1]));
                float2 p1 = make_float2(to_tf32(accs[nt][2]), to_tf32(accs[nt][3]));
                *(float2*)&Ps[row * SP + col]       = p0;
                *(float2*)&Ps[(row + 8) * SP + col] = p1;
            }
        }
        __syncwarp();

        // ---- acco += P @ V (P A-frags are warp-local rows only) ----
        #pragma unroll
        for (int ks = 0; ks < 8; ks++) {
            const int kb = ks * 8;
            const int row = wp * 16 + g;
            uint32_t a[4];
            a[0] = __float_as_uint(Ps[row * SP + kb + t4]);
            a[1] = __float_as_uint(Ps[(row + 8) * SP + kb + t4]);
            a[2] = __float_as_uint(Ps[row * SP + kb + t4 + 4]);
            a[3] = __float_as_uint(Ps[(row + 8) * SP + kb + t4 + 4]);
            #pragma unroll
            for (int nt = 0; nt < 8; nt++) {
                uint32_t bf[2];
                const int col = nt * 8 + g;
                bf[0] = __float_as_uint(Vs[(kb + t4) * SV + col]);
                bf[1] = __float_as_uint(Vs[(kb + t4 + 4) * SV + col]);
                mma8(acco[nt], a, bf);
            }
        }
        __syncthreads();   // protect K/V before next tile's loads
    }

    // ---- finalize: normalized per-path tiles -> P buffers, combine, store ----
    {
        const float sc = path ? 0.5f : 1.0f;
        const float inv0 = sc / l0, inv1 = sc / l1;
        const int row = wp * 16 + g;
        #pragma unroll
        for (int nt = 0; nt < 8; nt++) {
            const int col = nt * 8 + 2 * t4;
            *(float2*)&Ps[row * SP + col]       = make_float2(acco[nt][0] * inv0, acco[nt][1] * inv0);
            *(float2*)&Ps[(row + 8) * SP + col] = make_float2(acco[nt][2] * inv1, acco[nt][3] * inv1);
        }
    }
    __syncthreads();
    for (int i = tid; i < 1024; i += 256) {
        int row = i >> 4, c4 = i & 15;
        float4 a = *(float4*)&P1s[row * SP + c4 * 4];
        float4 c = *(float4*)&P2s[row * SP + c4 * 4];
        float4 r = make_float4(a.x - c.x, a.y - c.y, a.z - c.z, a.w - c.w);
        *(float4*)&out[(qrow0 + row) * DD + (size_t)h * 64 + c4 * 4] = r;
    }
}

static const size_t ATTN_SMEM = (4 * 64 * SP + 64 * SV) * sizeof(float);  // 88064 B

extern "C" void kernel_launch(void* const* d_in, const int* in_sizes, int n_in,
                              void* d_out, int out_size) {
    (void)in_sizes; (void)n_in; (void)out_size;
    const float* x  = (const float*)d_in[0];
    const float* Wq = (const float*)d_in[1];
    const float* bq = (const float*)d_in[2];
    const float* Wk = (const float*)d_in[3];
    const float* bk = (const float*)d_in[4];
    const float* Wv = (const float*)d_in[5];
    const float* bv = (const float*)d_in[6];
    float* out = (float*)d_out;

    cudaFuncSetAttribute(diff_attn, cudaFuncAttributeMaxDynamicSharedMemorySize,
                         (int)ATTN_SMEM);

    dim3 blk(256);
    proj_mma<0><<<dim3(TD / 64, MROWS / 128), blk>>>(x, Wq, bq, TD);
    proj_mma<1><<<dim3(TD / 64, MROWS / 128), blk>>>(x, Wk, bk, TD);
    proj_mma<2><<<dim3(DD / 64, MROWS / 128), blk>>>(x, Wv, bv, DD);
    diff_attn<<<dim3(NN / 64, HH, BB), blk, ATTN_SMEM>>>(out);
}

// round 4
// speedup vs baseline: 4.3010x; 1.1319x over previous
#include <cuda_runtime.h>
#include <cstdint>

#define BB 4
#define NN 1024
#define DD 512
#define HH 8
#define TD (2*DD)          // 1024
#define MROWS (BB*NN)      // 4096

// Scratch for projected Q, K, V (tf32-pre-rounded by projection epilogues)
__device__ float g_Q[(size_t)MROWS * TD];
__device__ float g_K[(size_t)MROWS * TD];
__device__ float g_V[(size_t)MROWS * DD];

__device__ __forceinline__ float to_tf32(float x) {
    unsigned u;
    asm("cvt.rna.tf32.f32 %0, %1;" : "=r"(u) : "f"(x));
    return __uint_as_float(u);
}

__device__ __forceinline__ void mma8(float* c, const uint32_t* a, const uint32_t* b) {
    asm volatile(
        "mma.sync.aligned.m16n8k8.row.col.f32.tf32.tf32.f32 "
        "{%0,%1,%2,%3},{%4,%5,%6,%7},{%8,%9},{%0,%1,%2,%3};"
        : "+f"(c[0]), "+f"(c[1]), "+f"(c[2]), "+f"(c[3])
        : "r"(a[0]), "r"(a[1]), "r"(a[2]), "r"(a[3]), "r"(b[0]), "r"(b[1]));
}

__device__ __forceinline__ void cpa16(uint32_t saddr, const void* gptr) {
    asm volatile("cp.async.cg.shared.global [%0], [%1], 16;" :: "r"(saddr), "l"(gptr));
}
__device__ __forceinline__ void cpa_commit() {
    asm volatile("cp.async.commit_group;");
}
__device__ __forceinline__ void cpa_wait0() {
    asm volatile("cp.async.wait_group 0;");
}

// ----------------------------------------------------------------------------
// Projection GEMM (tf32 mma): C[M,N] = tf32_round(A[M,512] @ W[512,N] + bias)
// ----------------------------------------------------------------------------
#define SA 36
#define SB 72

template<int WHICH>
__global__ __launch_bounds__(256) void proj_mma(const float* __restrict__ A,
                                                const float* __restrict__ W,
                                                const float* __restrict__ bias,
                                                int N) {
    __shared__ float As[128 * SA];
    __shared__ float Bs[32 * SB];
    float* C = (WHICH == 0) ? g_Q : (WHICH == 1) ? g_K : g_V;

    const int tid = threadIdx.x, lane = tid & 31, w = tid >> 5;
    const int wm = w >> 1, wn = w & 1;
    const int g = lane >> 2, t4 = lane & 3;

    float acc[2][4][4] = {};
    const float* Ab = A + (size_t)blockIdx.y * 128 * 512;
    const float* Wb = W + (size_t)blockIdx.x * 64;

    for (int k0 = 0; k0 < 512; k0 += 32) {
        #pragma unroll
        for (int i = tid; i < 128 * 32; i += 256) {
            int r = i >> 5, c = i & 31;
            As[r * SA + c] = to_tf32(Ab[(size_t)r * 512 + k0 + c]);
        }
        #pragma unroll
        for (int i = tid; i < 32 * 64; i += 256) {
            int r = i >> 6, c = i & 63;
            Bs[r * SB + c] = to_tf32(Wb[(size_t)(k0 + r) * N + c]);
        }
        __syncthreads();

        #pragma unroll
        for (int ks = 0; ks < 4; ks++) {
            const int kb = ks * 8;
            uint32_t a[2][4], bf[4][2];
            #pragma unroll
            for (int mt = 0; mt < 2; mt++) {
                int row = wm * 32 + mt * 16 + g;
                a[mt][0] = __float_as_uint(As[row * SA + kb + t4]);
                a[mt][1] = __float_as_uint(As[(row + 8) * SA + kb + t4]);
                a[mt][2] = __float_as_uint(As[row * SA + kb + t4 + 4]);
                a[mt][3] = __float_as_uint(As[(row + 8) * SA + kb + t4 + 4]);
            }
            #pragma unroll
            for (int nt = 0; nt < 4; nt++) {
                int col = wn * 32 + nt * 8 + g;
                bf[nt][0] = __float_as_uint(Bs[(kb + t4) * SB + col]);
                bf[nt][1] = __float_as_uint(Bs[(kb + t4 + 4) * SB + col]);
            }
            #pragma unroll
            for (int mt = 0; mt < 2; mt++)
                #pragma unroll
                for (int nt = 0; nt < 4; nt++)
                    mma8(acc[mt][nt], a[mt], bf[nt]);
        }
        __syncthreads();
    }

    #pragma unroll
    for (int mt = 0; mt < 2; mt++) {
        int row0 = blockIdx.y * 128 + wm * 32 + mt * 16 + g;
        #pragma unroll
        for (int nt = 0; nt < 4; nt++) {
            int col = blockIdx.x * 64 + wn * 32 + nt * 8 + 2 * t4;
            C[(size_t)row0 * N + col]           = to_tf32(acc[mt][nt][0] + bias[col]);
            C[(size_t)row0 * N + col + 1]       = to_tf32(acc[mt][nt][1] + bias[col + 1]);
            C[(size_t)(row0 + 8) * N + col]     = to_tf32(acc[mt][nt][2] + bias[col]);
            C[(size_t)(row0 + 8) * N + col + 1] = to_tf32(acc[mt][nt][3] + bias[col + 1]);
        }
    }
}

// ----------------------------------------------------------------------------
// Differential attention: 512 threads, 128 q-rows/CTA, cp.async double-buffered
// K (swizzled [key][128]) + V. Warp = 16 q-rows x 64 keys of one path.
// ----------------------------------------------------------------------------
#define SP 68              // P staging stride
#define SV 72              // V stride
#define KBUF (64*128)      // floats per K buffer (swizzled, no pad)
#define VBUF (64*SV)

__global__ __launch_bounds__(512, 1) void diff_attn(float* __restrict__ out) {
    extern __shared__ float sm[];
    float* Ksm = sm;                    // [2][64][128] swizzled: d ^= 4*(k&7)
    float* Vsm = Ksm + 2 * KBUF;        // [2][64][SV]
    float* P1s = Vsm + 2 * VBUF;        // [128][SP]  path-1 P / staging
    float* P2s = P1s + 128 * SP;        // path-2

    const int qt = blockIdx.x, h = blockIdx.y, b = blockIdx.z;
    const int tid = threadIdx.x, lane = tid & 31, w = tid >> 5;
    const int path = w >> 3;            // warps 0-7 path1, 8-15 path2
    const int wp = w & 7;               // 16-row block
    const int g = lane >> 2, t4 = lane & 3;
    const size_t qrow0 = (size_t)b * NN + (size_t)qt * 128;

    float* Ps = path ? P2s : P1s;
    const int dbase = path * 64;

    // ---- prefetch tile 0 ----
    {
        const size_t krow0 = (size_t)b * NN;
        #pragma unroll
        for (int j = 0; j < 4; j++) {
            int i = tid + j * 512;               // 0..2047
            int k = i >> 5, c4 = i & 31;
            uint32_t ds = (uint32_t)__cvta_generic_to_shared(
                Ksm + k * 128 + ((c4 * 4) ^ (4 * (k & 7))));
            cpa16(ds, &g_K[(krow0 + k) * TD + (size_t)h * 128 + c4 * 4]);
        }
        #pragma unroll
        for (int j = 0; j < 2; j++) {
            int i = tid + j * 512;               // 0..1023
            int k = i >> 4, c4 = i & 15;
            uint32_t ds = (uint32_t)__cvta_generic_to_shared(Vsm + k * SV + c4 * 4);
            cpa16(ds, &g_V[(krow0 + k) * DD + (size_t)h * 64 + c4 * 4]);
        }
        cpa_commit();
    }

    // ---- stage Q into P buffers, lift to A-fragments ----
    for (int i = tid; i < 4096; i += 512) {      // 128 rows x 32 f4
        int row = i >> 5, c4 = i & 31;
        const float4 v = *(const float4*)&g_Q[(qrow0 + row) * TD + (size_t)h * 128 + c4 * 4];
        float* dst = (c4 < 16 ? P1s + row * SP + c4 * 4
                              : P2s + row * SP + (c4 - 16) * 4);
        *(float4*)dst = v;
    }
    __syncthreads();

    uint32_t qa[8][4];
    {
        const int row = wp * 16 + g;
        #pragma unroll
        for (int ks = 0; ks < 8; ks++) {
            const int kb = ks * 8;
            qa[ks][0] = __float_as_uint(Ps[row * SP + kb + t4] * 0.125f);
            qa[ks][1] = __float_as_uint(Ps[(row + 8) * SP + kb + t4] * 0.125f);
            qa[ks][2] = __float_as_uint(Ps[row * SP + kb + t4 + 4] * 0.125f);
            qa[ks][3] = __float_as_uint(Ps[(row + 8) * SP + kb + t4 + 4] * 0.125f);
        }
    }

    float acco[8][4] = {};
    float m0 = -1e30f, m1 = -1e30f, l0 = 0.f, l1 = 0.f;
    const int xr = 4 * g;               // K swizzle term for B-frag reads

    for (int kt = 0; kt < NN / 64; kt++) {
        const int buf = kt & 1;
        cpa_wait0();
        __syncthreads();                 // tile kt ready; compute kt-1 done everywhere

        if (kt + 1 < NN / 64) {          // prefetch kt+1 into other buffer
            const size_t krow0 = (size_t)b * NN + (size_t)(kt + 1) * 64;
            float* Kd = Ksm + (buf ^ 1) * KBUF;
            float* Vd = Vsm + (buf ^ 1) * VBUF;
            #pragma unroll
            for (int j = 0; j < 4; j++) {
                int i = tid + j * 512;
                int k = i >> 5, c4 = i & 31;
                uint32_t ds = (uint32_t)__cvta_generic_to_shared(
                    Kd + k * 128 + ((c4 * 4) ^ (4 * (k & 7))));
                cpa16(ds, &g_K[(krow0 + k) * TD + (size_t)h * 128 + c4 * 4]);
            }
            #pragma unroll
            for (int j = 0; j < 2; j++) {
                int i = tid + j * 512;
                int k = i >> 4, c4 = i & 15;
                uint32_t ds = (uint32_t)__cvta_generic_to_shared(Vd + k * SV + c4 * 4);
                cpa16(ds, &g_V[(krow0 + k) * DD + (size_t)h * 64 + c4 * 4]);
            }
            cpa_commit();
        }

        const float* Kb = Ksm + buf * KBUF;
        const float* Vb = Vsm + buf * VBUF;

        // ---- S = Q @ K^T ----
        float accs[8][4] = {};
        #pragma unroll
        for (int ks = 0; ks < 8; ks++) {
            const int kb = ks * 8;
            #pragma unroll
            for (int nt = 0; nt < 8; nt++) {
                uint32_t bf[2];
                const int col = nt * 8 + g;
                bf[0] = __float_as_uint(Kb[col * 128 + ((dbase + kb + t4) ^ xr)]);
                bf[1] = __float_as_uint(Kb[col * 128 + ((dbase + kb + t4 + 4) ^ xr)]);
                mma8(accs[nt], qa[ks], bf);
            }
        }

        // ---- online softmax in registers ----
        float tm0 = -1e30f, tm1 = -1e30f;
        #pragma unroll
        for (int nt = 0; nt < 8; nt++) {
            tm0 = fmaxf(tm0, fmaxf(accs[nt][0], accs[nt][1]));
            tm1 = fmaxf(tm1, fmaxf(accs[nt][2], accs[nt][3]));
        }
        tm0 = fmaxf(tm0, __shfl_xor_sync(0xffffffffu, tm0, 1));
        tm0 = fmaxf(tm0, __shfl_xor_sync(0xffffffffu, tm0, 2));
        tm1 = fmaxf(tm1, __shfl_xor_sync(0xffffffffu, tm1, 1));
        tm1 = fmaxf(tm1, __shfl_xor_sync(0xffffffffu, tm1, 2));
        const float mn0 = fmaxf(m0, tm0), mn1 = fmaxf(m1, tm1);
        const float al0 = __expf(m0 - mn0), al1 = __expf(m1 - mn1);
        float s0 = 0.f, s1 = 0.f;
        #pragma unroll
        for (int nt = 0; nt < 8; nt++) {
            accs[nt][0] = __expf(accs[nt][0] - mn0);
            accs[nt][1] = __expf(accs[nt][1] - mn0);
            accs[nt][2] = __expf(accs[nt][2] - mn1);
            accs[nt][3] = __expf(accs[nt][3] - mn1);
            s0 += accs[nt][0] + accs[nt][1];
            s1 += accs[nt][2] + accs[nt][3];
        }
        s0 += __shfl_xor_sync(0xffffffffu, s0, 1);
        s0 += __shfl_xor_sync(0xffffffffu, s0, 2);
        s1 += __shfl_xor_sync(0xffffffffu, s1, 1);
        s1 += __shfl_xor_sync(0xffffffffu, s1, 2);
        l0 = l0 * al0 + s0;  m0 = mn0;
        l1 = l1 * al1 + s1;  m1 = mn1;

        // ---- rescale acc; stage P (tf32) through warp-private smem rows ----
        {
            const int row = wp * 16 + g;
            #pragma unroll
            for (int nt = 0; nt < 8; nt++) {
                acco[nt][0] *= al0;  acco[nt][1] *= al0;
                acco[nt][2] *= al1;  acco[nt][3] *= al1;
                const int col = nt * 8 + 2 * t4;
                *(float2*)&Ps[row * SP + col] =
                    make_float2(to_tf32(accs[nt][0]), to_tf32(accs[nt][1]));
                *(float2*)&Ps[(row + 8) * SP + col] =
                    make_float2(to_tf32(accs[nt][2]), to_tf32(accs[nt][3]));
            }
        }
        __syncwarp();

        // ---- acco += P @ V ----
        #pragma unroll
        for (int ks = 0; ks < 8; ks++) {
            const int kb = ks * 8;
            const int row = wp * 16 + g;
            uint32_t a[4];
            a[0] = __float_as_uint(Ps[row * SP + kb + t4]);
            a[1] = __float_as_uint(Ps[(row + 8) * SP + kb + t4]);
            a[2] = __float_as_uint(Ps[row * SP + kb + t4 + 4]);
            a[3] = __float_as_uint(Ps[(row + 8) * SP + kb + t4 + 4]);
            #pragma unroll
            for (int nt = 0; nt < 8; nt++) {
                uint32_t bf[2];
                const int col = nt * 8 + g;
                bf[0] = __float_as_uint(Vb[(kb + t4) * SV + col]);
                bf[1] = __float_as_uint(Vb[(kb + t4 + 4) * SV + col]);
                mma8(acco[nt], a, bf);
            }
        }
        // no trailing barrier: next iteration's wait+syncthreads protects buffers
    }

    // ---- finalize: per-path normalized tiles -> P, combine, store ----
    {
        const float sc = path ? 0.5f : 1.0f;
        const float inv0 = sc / l0, inv1 = sc / l1;
        const int row = wp * 16 + g;
        #pragma unroll
        for (int nt = 0; nt < 8; nt++) {
            const int col = nt * 8 + 2 * t4;
            *(float2*)&Ps[row * SP + col]       = make_float2(acco[nt][0] * inv0, acco[nt][1] * inv0);
            *(float2*)&Ps[(row + 8) * SP + col] = make_float2(acco[nt][2] * inv1, acco[nt][3] * inv1);
        }
    }
    __syncthreads();
    for (int i = tid; i < 2048; i += 512) {      // 128 rows x 16 f4
        int row = i >> 4, c4 = i & 15;
        float4 a = *(float4*)&P1s[row * SP + c4 * 4];
        float4 c = *(float4*)&P2s[row * SP + c4 * 4];
        float4 r = make_float4(a.x - c.x, a.y - c.y, a.z - c.z, a.w - c.w);
        *(float4*)&out[(qrow0 + row) * DD + (size_t)h * 64 + c4 * 4] = r;
    }
}

static const size_t ATTN_SMEM = (2 * KBUF + 2 * VBUF + 2 * 128 * SP) * sizeof(float); // 172032 B

extern "C" void kernel_launch(void* const* d_in, const int* in_sizes, int n_in,
                              void* d_out, int out_size) {
    (void)in_sizes; (void)n_in; (void)out_size;
    const float* x  = (const float*)d_in[0];
    const float* Wq = (const float*)d_in[1];
    const float* bq = (const float*)d_in[2];
    const float* Wk = (const float*)d_in[3];
    const float* bk = (const float*)d_in[4];
    const float* Wv = (const float*)d_in[5];
    const float* bv = (const float*)d_in[6];
    float* out = (float*)d_out;

    cudaFuncSetAttribute(diff_attn, cudaFuncAttributeMaxDynamicSharedMemorySize,
                         (int)ATTN_SMEM);

    dim3 blk(256);
    proj_mma<0><<<dim3(TD / 64, MROWS / 128), blk>>>(x, Wq, bq, TD);
    proj_mma<1><<<dim3(TD / 64, MROWS / 128), blk>>>(x, Wk, bk, TD);
    proj_mma<2><<<dim3(DD / 64, MROWS / 128), blk>>>(x, Wv, bv, DD);
    diff_attn<<<dim3(NN / 128, HH, BB), 512, ATTN_SMEM>>>(out);
}

// round 5
// speedup vs baseline: 7.2703x; 1.6904x over previous
#include <cuda_runtime.h>
#include <cuda_fp16.h>
#include <cstdint>

#define BB 4
#define NN 1024
#define DD 512
#define HH 8
#define TD 1024            // Q/K projected width (halves)
#define MROWS (BB*NN)      // 4096

// Projected activations, fp16. V stored transposed: [b*8+h][d][token]
__device__ __half g_Q[(size_t)MROWS * TD];
__device__ __half g_K[(size_t)MROWS * TD];
__device__ __half g_Vt[(size_t)BB * HH * 64 * NN];

__device__ __forceinline__ uint32_t f2h2(float lo, float hi) {
    uint32_t r;
    asm("cvt.rn.f16x2.f32 %0, %1, %2;" : "=r"(r) : "f"(hi), "f"(lo));
    return r;
}

// C(16x8,f32) += A(16x16,f16) @ B(16x8,f16)
__device__ __forceinline__ void mma16(float* c, uint32_t a0, uint32_t a1,
                                      uint32_t a2, uint32_t a3,
                                      uint32_t b0, uint32_t b1) {
    asm volatile(
        "mma.sync.aligned.m16n8k16.row.col.f32.f16.f16.f32 "
        "{%0,%1,%2,%3},{%4,%5,%6,%7},{%8,%9},{%0,%1,%2,%3};"
        : "+f"(c[0]), "+f"(c[1]), "+f"(c[2]), "+f"(c[3])
        : "r"(a0), "r"(a1), "r"(a2), "r"(a3), "r"(b0), "r"(b1));
}

__device__ __forceinline__ void cpa16(uint32_t saddr, const void* gptr) {
    asm volatile("cp.async.cg.shared.global [%0], [%1], 16;" :: "r"(saddr), "l"(gptr));
}
__device__ __forceinline__ void cpa_commit() { asm volatile("cp.async.commit_group;"); }
__device__ __forceinline__ void cpa_wait0()  { asm volatile("cp.async.wait_group 0;"); }

// ----------------------------------------------------------------------------
// Fused projection: bx<16 -> Q (scaled 1/8), bx<32 -> K, else -> V (transposed)
// Block tile 128x64, fp16 m16n8k16, 8 warps (4x2), warp tile 32x32.
// ----------------------------------------------------------------------------
__global__ __launch_bounds__(256) void proj_all(
    const float* __restrict__ x,
    const float* __restrict__ Wq, const float* __restrict__ bq,
    const float* __restrict__ Wk, const float* __restrict__ bk,
    const float* __restrict__ Wv, const float* __restrict__ bv) {
    __shared__ __half As[128 * 40];    // [row][k32] pad->40
    __shared__ __half Bs[64 * 40];     // [n][k32] (W^T) pad->40

    const int bx = blockIdx.x, by = blockIdx.y;
    const float *W, *bias;
    int N, colb, sel;
    if (bx < 16)      { W = Wq; bias = bq; N = 1024; colb = bx * 64;        sel = 0; }
    else if (bx < 32) { W = Wk; bias = bk; N = 1024; colb = (bx - 16) * 64; sel = 1; }
    else              { W = Wv; bias = bv; N = 512;  colb = (bx - 32) * 64; sel = 2; }

    const int tid = threadIdx.x, lane = tid & 31, w = tid >> 5;
    const int wm = w >> 1, wn = w & 1;
    const int g = lane >> 2, t4 = lane & 3;
    uint32_t* As2 = (uint32_t*)As;     // half2 units, stride 20
    uint32_t* Bs2 = (uint32_t*)Bs;

    float acc[2][4][4] = {};
    const float* Ab = x + (size_t)by * 128 * 512;

    for (int k0 = 0; k0 < 512; k0 += 32) {
        #pragma unroll
        for (int i = tid; i < 2048; i += 256) {     // A: 128 rows x 16 half2
            int r = i >> 4, c2 = i & 15;
            float2 v = *(const float2*)&Ab[(size_t)r * 512 + k0 + 2 * c2];
            As2[r * 20 + c2] = f2h2(v.x, v.y);
        }
        #pragma unroll
        for (int i = tid; i < 2048; i += 256) {     // W^T: [n][k]
            int r = i >> 6, c = i & 63;
            Bs[c * 40 + r] = __float2half_rn(W[(size_t)(k0 + r) * N + colb + c]);
        }
        __syncthreads();

        #pragma unroll
        for (int kk = 0; kk < 2; kk++) {
            uint32_t a[2][4], bf[4][2];
            #pragma unroll
            for (int mt = 0; mt < 2; mt++) {
                int row = wm * 32 + mt * 16 + g;
                a[mt][0] = As2[row * 20 + kk * 8 + t4];
                a[mt][1] = As2[(row + 8) * 20 + kk * 8 + t4];
                a[mt][2] = As2[row * 20 + kk * 8 + t4 + 4];
                a[mt][3] = As2[(row + 8) * 20 + kk * 8 + t4 + 4];
            }
            #pragma unroll
            for (int nt = 0; nt < 4; nt++) {
                int col = wn * 32 + nt * 8 + g;
                bf[nt][0] = Bs2[col * 20 + kk * 8 + t4];
                bf[nt][1] = Bs2[col * 20 + kk * 8 + t4 + 4];
            }
            #pragma unroll
            for (int mt = 0; mt < 2; mt++)
                #pragma unroll
                for (int nt = 0; nt < 4; nt++)
                    mma16(acc[mt][nt], a[mt][0], a[mt][1], a[mt][2], a[mt][3],
                          bf[nt][0], bf[nt][1]);
        }
        __syncthreads();
    }

    const float qs = (sel == 0) ? 0.125f : 1.0f;
    #pragma unroll
    for (int mt = 0; mt < 2; mt++) {
        int row0 = by * 128 + wm * 32 + mt * 16 + g;
        #pragma unroll
        for (int nt = 0; nt < 4; nt++) {
            int col = colb + wn * 32 + nt * 8 + 2 * t4;
            float b0 = bias[col], b1 = bias[col + 1];
            float v00 = (acc[mt][nt][0] + b0) * qs, v01 = (acc[mt][nt][1] + b1) * qs;
            float v10 = (acc[mt][nt][2] + b0) * qs, v11 = (acc[mt][nt][3] + b1) * qs;
            if (sel < 2) {
                __half* dst = sel ? g_K : g_Q;
                *(uint32_t*)&dst[(size_t)row0 * 1024 + col]       = f2h2(v00, v01);
                *(uint32_t*)&dst[(size_t)(row0 + 8) * 1024 + col] = f2h2(v10, v11);
            } else {
                int hh = col >> 6, d = col & 63;
                int bb = row0 >> 10, tok = row0 & 1023;
                size_t base = ((size_t)(bb * 8 + hh) * 64);
                g_Vt[(base + d) * NN + tok]         = __float2half_rn(v00);
                g_Vt[(base + d + 1) * NN + tok]     = __float2half_rn(v01);
                g_Vt[(base + d) * NN + tok + 8]     = __float2half_rn(v10);
                g_Vt[(base + d + 1) * NN + tok + 8] = __float2half_rn(v11);
            }
        }
    }
}

// ----------------------------------------------------------------------------
// Differential attention, fp16 mma. 512 threads, 128 q-rows/CTA.
// K smem [key][128h] swizzled; Vt smem [d][64h] swizzled; P stays in registers.
// ----------------------------------------------------------------------------
#define KWORDS 4096        // 64 rows x 64 words per K buffer
#define VWORDS 2048        // 64 rows x 32 words per V buffer

__global__ __launch_bounds__(512, 1) void diff_attn(float* __restrict__ out) {
    extern __shared__ uint32_t smw[];
    uint32_t* ksm = smw;                    // [2][64][64w], chunk-swizzled
    uint32_t* vsm = ksm + 2 * KWORDS;       // [2][64][32w]
    float*    osm = (float*)(vsm + 2 * VWORDS);  // [128][68] f32 (aliases qsm)
    uint32_t* qsm = (uint32_t*)osm;         // [128][64w], same swizzle as K

    const int qt = blockIdx.x, h = blockIdx.y, b = blockIdx.z;
    const int tid = threadIdx.x, lane = tid & 31, w = tid >> 5;
    const int path = w >> 3, wp = w & 7;
    const int g = lane >> 2, t4 = lane & 3;
    const size_t qrow0 = (size_t)b * NN + (size_t)qt * 128;
    const size_t vhbase = (size_t)(b * 8 + h) * 64;

    // ---- prefetch K/V tile 0 ----
    {
        const size_t krow0 = (size_t)b * NN;
        #pragma unroll
        for (int j = 0; j < 2; j++) {
            int i = tid + j * 512;               // 1024 chunks: K 64x16
            int key = i >> 4, c = i & 15;
            uint32_t ds = (uint32_t)__cvta_generic_to_shared(ksm) +
                          key * 256 + 16 * ((c & 8) | ((c & 7) ^ (key & 7)));
            cpa16(ds, &g_K[(krow0 + key) * TD + (size_t)h * 128 + c * 8]);
        }
        {
            int d = tid >> 3, c = tid & 7;       // 512 chunks: V 64x8
            uint32_t ds = (uint32_t)__cvta_generic_to_shared(vsm) +
                          d * 128 + 16 * (c ^ (d & 7));
            cpa16(ds, &g_Vt[(vhbase + d) * NN + c * 8]);
        }
        cpa_commit();
    }
    // ---- stage Q (cp.async into qsm, K-style swizzle) ----
    #pragma unroll
    for (int j = 0; j < 4; j++) {
        int i = tid + j * 512;                   // 2048 chunks: Q 128x16
        int row = i >> 4, c = i & 15;
        uint32_t ds = (uint32_t)__cvta_generic_to_shared(qsm) +
                      row * 256 + 16 * ((c & 8) | ((c & 7) ^ (row & 7)));
        cpa16(ds, &g_Q[(qrow0 + row) * TD + (size_t)h * 128 + c * 8]);
    }
    cpa_commit();
    cpa_wait0();
    __syncthreads();

    // ---- lift Q to A-fragments (4 k16-steps over this path's 64 dims) ----
    uint32_t qa[4][4];
    {
        const int rq = wp * 16 + g;
        #pragma unroll
        for (int ks = 0; ks < 4; ks++) {
            int c0 = (path * 8) | ((2 * ks) ^ g);
            int c1 = (path * 8) | ((2 * ks + 1) ^ g);
            qa[ks][0] = qsm[rq * 64 + 4 * c0 + t4];
            qa[ks][1] = qsm[(rq + 8) * 64 + 4 * c0 + t4];
            qa[ks][2] = qsm[rq * 64 + 4 * c1 + t4];
            qa[ks][3] = qsm[(rq + 8) * 64 + 4 * c1 + t4];
        }
    }

    float acco[8][4] = {};
    float m0 = -1e30f, m1 = -1e30f, l0 = 0.f, l1 = 0.f;

    for (int kt = 0; kt < NN / 64; kt++) {
        const int buf = kt & 1;
        cpa_wait0();
        __syncthreads();

        if (kt + 1 < NN / 64) {
            const size_t krow0 = (size_t)b * NN + (size_t)(kt + 1) * 64;
            const int klocal = (kt + 1) * 64;
            uint32_t kb_s = (uint32_t)__cvta_generic_to_shared(ksm + (buf ^ 1) * KWORDS);
            uint32_t vb_s = (uint32_t)__cvta_generic_to_shared(vsm + (buf ^ 1) * VWORDS);
            #pragma unroll
            for (int j = 0; j < 2; j++) {
                int i = tid + j * 512;
                int key = i >> 4, c = i & 15;
                uint32_t ds = kb_s + key * 256 + 16 * ((c & 8) | ((c & 7) ^ (key & 7)));
                cpa16(ds, &g_K[(krow0 + key) * TD + (size_t)h * 128 + c * 8]);
            }
            {
                int d = tid >> 3, c = tid & 7;
                uint32_t ds = vb_s + d * 128 + 16 * (c ^ (d & 7));
                cpa16(ds, &g_Vt[(vhbase + d) * NN + klocal + c * 8]);
            }
            cpa_commit();
        }

        const uint32_t* Kb = ksm + buf * KWORDS;
        const uint32_t* Vb = vsm + buf * VWORDS;

        // ---- S = Q @ K^T  (16 q-rows x 64 keys per warp) ----
        float accs[8][4] = {};
        #pragma unroll
        for (int ks = 0; ks < 4; ks++) {
            #pragma unroll
            for (int nt = 0; nt < 8; nt++) {
                const int key = nt * 8 + g;
                uint32_t b0 = Kb[key * 64 + 4 * ((path * 8) | ((2 * ks) ^ g)) + t4];
                uint32_t b1 = Kb[key * 64 + 4 * ((path * 8) | ((2 * ks + 1) ^ g)) + t4];
                mma16(accs[nt], qa[ks][0], qa[ks][1], qa[ks][2], qa[ks][3], b0, b1);
            }
        }

        // ---- online softmax in registers ----
        float tm0 = -1e30f, tm1 = -1e30f;
        #pragma unroll
        for (int nt = 0; nt < 8; nt++) {
            tm0 = fmaxf(tm0, fmaxf(accs[nt][0], accs[nt][1]));
            tm1 = fmaxf(tm1, fmaxf(accs[nt][2], accs[nt][3]));
        }
        tm0 = fmaxf(tm0, __shfl_xor_sync(0xffffffffu, tm0, 1));
        tm0 = fmaxf(tm0, __shfl_xor_sync(0xffffffffu, tm0, 2));
        tm1 = fmaxf(tm1, __shfl_xor_sync(0xffffffffu, tm1, 1));
        tm1 = fmaxf(tm1, __shfl_xor_sync(0xffffffffu, tm1, 2));
        const float mn0 = fmaxf(m0, tm0), mn1 = fmaxf(m1, tm1);
        const float al0 = __expf(m0 - mn0), al1 = __expf(m1 - mn1);
        float s0 = 0.f, s1 = 0.f;
        #pragma unroll
        for (int nt = 0; nt < 8; nt++) {
            accs[nt][0] = __expf(accs[nt][0] - mn0);
            accs[nt][1] = __expf(accs[nt][1] - mn0);
            accs[nt][2] = __expf(accs[nt][2] - mn1);
            accs[nt][3] = __expf(accs[nt][3] - mn1);
            s0 += accs[nt][0] + accs[nt][1];
            s1 += accs[nt][2] + accs[nt][3];
        }
        s0 += __shfl_xor_sync(0xffffffffu, s0, 1);
        s0 += __shfl_xor_sync(0xffffffffu, s0, 2);
        s1 += __shfl_xor_sync(0xffffffffu, s1, 1);
        s1 += __shfl_xor_sync(0xffffffffu, s1, 2);
        l0 = l0 * al0 + s0;  m0 = mn0;
        l1 = l1 * al1 + s1;  m1 = mn1;

        // ---- rescale acco; P->A-frags IN REGISTERS; acco += P @ V ----
        #pragma unroll
        for (int nt = 0; nt < 8; nt++) {
            acco[nt][0] *= al0;  acco[nt][1] *= al0;
            acco[nt][2] *= al1;  acco[nt][3] *= al1;
        }
        #pragma unroll
        for (int ks = 0; ks < 4; ks++) {
            uint32_t a0 = f2h2(accs[2 * ks][0],     accs[2 * ks][1]);
            uint32_t a1 = f2h2(accs[2 * ks][2],     accs[2 * ks][3]);
            uint32_t a2 = f2h2(accs[2 * ks + 1][0], accs[2 * ks + 1][1]);
            uint32_t a3 = f2h2(accs[2 * ks + 1][2], accs[2 * ks + 1][3]);
            #pragma unroll
            for (int nt = 0; nt < 8; nt++) {
                const int d = nt * 8 + g;
                uint32_t b0 = Vb[d * 32 + 4 * ((2 * ks) ^ g) + t4];
                uint32_t b1 = Vb[d * 32 + 4 * ((2 * ks + 1) ^ g) + t4];
                mma16(acco[nt], a0, a1, a2, a3, b0, b1);
            }
        }
    }

    // ---- combine: path2 stages to osm; path1 subtracts and writes gmem ----
    if (path == 1) {
        const float inv0 = 0.5f / l0, inv1 = 0.5f / l1;
        const int row = wp * 16 + g;
        #pragma unroll
        for (int nt = 0; nt < 8; nt++) {
            const int col = nt * 8 + 2 * t4;
            *(float2*)&osm[row * 68 + col]       = make_float2(acco[nt][0] * inv0, acco[nt][1] * inv0);
            *(float2*)&osm[(row + 8) * 68 + col] = make_float2(acco[nt][2] * inv1, acco[nt][3] * inv1);
        }
    }
    __syncthreads();
    if (path == 0) {
        const float inv0 = 1.0f / l0, inv1 = 1.0f / l1;
        const int row = wp * 16 + g;
        #pragma unroll
        for (int nt = 0; nt < 8; nt++) {
            const int col = nt * 8 + 2 * t4;
            float2 o0 = *(float2*)&osm[row * 68 + col];
            float2 o1 = *(float2*)&osm[(row + 8) * 68 + col];
            float2 r0 = make_float2(acco[nt][0] * inv0 - o0.x, acco[nt][1] * inv0 - o0.y);
            float2 r1 = make_float2(acco[nt][2] * inv1 - o1.x, acco[nt][3] * inv1 - o1.y);
            *(float2*)&out[(qrow0 + row) * DD + (size_t)h * 64 + col]     = r0;
            *(float2*)&out[(qrow0 + row + 8) * DD + (size_t)h * 64 + col] = r1;
        }
    }
}

static const size_t ATTN_SMEM = (2 * KWORDS + 2 * VWORDS + 128 * 68) * 4;  // 83968 B

extern "C" void kernel_launch(void* const* d_in, const int* in_sizes, int n_in,
                              void* d_out, int out_size) {
    (void)in_sizes; (void)n_in; (void)out_size;
    const float* x  = (const float*)d_in[0];
    const float* Wq = (const float*)d_in[1];
    const float* bq = (const float*)d_in[2];
    const float* Wk = (const float*)d_in[3];
    const float* bk = (const float*)d_in[4];
    const float* Wv = (const float*)d_in[5];
    const float* bv = (const float*)d_in[6];
    float* out = (float*)d_out;

    cudaFuncSetAttribute(diff_attn, cudaFuncAttributeMaxDynamicSharedMemorySize,
                         (int)ATTN_SMEM);

    proj_all<<<dim3(40, 32), 256>>>(x, Wq, bq, Wk, bk, Wv, bv);
    diff_attn<<<dim3(NN / 128, HH, BB), 512, ATTN_SMEM>>>(out);
}

// round 6
// speedup vs baseline: 10.1270x; 1.3929x over previous
#include <cuda_runtime.h>
#include <cuda_fp16.h>
#include <cstdint>

#define BB 4
#define NN 1024
#define DD 512
#define HH 8
#define TD 1024            // Q/K projected width
#define MROWS (BB*NN)      // 4096
#define NTOT 2560          // combined output columns: Q 1024 | K 1024 | V 512

// fp16 staging
__device__ __half g_Xh[(size_t)MROWS * 512];
__device__ __half g_Wt[(size_t)NTOT * 512];     // [n][k] (transposed weights)
__device__ float  g_bias[NTOT];
// Projected activations
__device__ __half g_Q[(size_t)MROWS * TD];
__device__ __half g_K[(size_t)MROWS * TD];
__device__ __half g_Vt[(size_t)BB * HH * 64 * NN];   // [b*8+h][d][token]

__device__ __forceinline__ uint32_t f2h2(float lo, float hi) {
    uint32_t r;
    asm("cvt.rn.f16x2.f32 %0, %1, %2;" : "=r"(r) : "f"(hi), "f"(lo));
    return r;
}

__device__ __forceinline__ void mma16(float* c, uint32_t a0, uint32_t a1,
                                      uint32_t a2, uint32_t a3,
                                      uint32_t b0, uint32_t b1) {
    asm volatile(
        "mma.sync.aligned.m16n8k16.row.col.f32.f16.f16.f32 "
        "{%0,%1,%2,%3},{%4,%5,%6,%7},{%8,%9},{%0,%1,%2,%3};"
        : "+f"(c[0]), "+f"(c[1]), "+f"(c[2]), "+f"(c[3])
        : "r"(a0), "r"(a1), "r"(a2), "r"(a3), "r"(b0), "r"(b1));
}

__device__ __forceinline__ void cpa16(uint32_t saddr, const void* gptr) {
    asm volatile("cp.async.cg.shared.global [%0], [%1], 16;" :: "r"(saddr), "l"(gptr));
}
__device__ __forceinline__ void cpa_commit() { asm volatile("cp.async.commit_group;"); }
__device__ __forceinline__ void cpa_wait0()  { asm volatile("cp.async.wait_group 0;"); }

// ----------------------------------------------------------------------------
// Convert: x -> g_Xh; Wq/Wk/Wv -> g_Wt (transposed, fp16); biases -> g_bias.
// grid.x = 1024 (x) + 1280 (W tiles) + 10 (bias)
// ----------------------------------------------------------------------------
__global__ __launch_bounds__(256) void convert_all(
    const float* __restrict__ x,
    const float* __restrict__ Wq, const float* __restrict__ bq,
    const float* __restrict__ Wk, const float* __restrict__ bk,
    const float* __restrict__ Wv, const float* __restrict__ bv) {
    const int bx = blockIdx.x, tid = threadIdx.x;
    if (bx < 1024) {                       // x: 2M floats, 8 per thread
        int base = bx * 2048 + tid * 8;
        float4 v0 = *(const float4*)&x[base];
        float4 v1 = *(const float4*)&x[base + 4];
        uint4 o;
        o.x = f2h2(v0.x, v0.y);  o.y = f2h2(v0.z, v0.w);
        o.z = f2h2(v1.x, v1.y);  o.w = f2h2(v1.z, v1.w);
        *(uint4*)&g_Xh[base] = o;
    } else if (bx < 1024 + 1280) {         // W 32x32 tile transpose
        __shared__ __half ts[32][33];
        int t = bx - 1024;
        const float* W; int N, kt, nt, nrow0;
        if (t < 512)      { W = Wq; N = 1024; kt = t >> 5;          nt = t & 31;          nrow0 = 0;    }
        else if (t < 1024){ W = Wk; N = 1024; kt = (t - 512) >> 5;  nt = (t - 512) & 31;  nrow0 = 1024; }
        else              { W = Wv; N = 512;  kt = (t - 1024) >> 4; nt = (t - 1024) & 15; nrow0 = 2048; }
        #pragma unroll
        for (int p = 0; p < 4; p++) {
            int r = p * 8 + (tid >> 5), c = tid & 31;
            ts[r][c] = __float2half_rn(W[(size_t)(kt * 32 + r) * N + nt * 32 + c]);
        }
        __syncthreads();
        #pragma unroll
        for (int p = 0; p < 4; p++) {
            int n = p * 8 + (tid >> 5), k = tid & 31;
            g_Wt[(size_t)(nrow0 + nt * 32 + n) * 512 + kt * 32 + k] = ts[k][n];
        }
    } else {                               // bias
        int i = (bx - 2304) * 256 + tid;
        if (i < NTOT)
            g_bias[i] = (i < 1024) ? bq[i] : (i < 2048) ? bk[i - 1024] : bv[i - 2048];
    }
}

// ----------------------------------------------------------------------------
// Pipelined fp16 projection GEMM: C[4096, 2560] = g_Xh @ g_Wt^T (+bias).
// 128x128 block tile, k-chunk 64, cp.async double-buffered, 8 warps (4x2).
// Output: cols<1024 -> Q (x0.125), <2048 -> K, else -> Vt (transposed).
// ----------------------------------------------------------------------------
#define PJSTG 4096          // half2 words per smem stage (128 rows x 32 words)

__global__ __launch_bounds__(256) void proj_mma(void) {
    extern __shared__ uint32_t smw[];
    uint32_t* asm_ = smw;               // [2][128][32w]
    uint32_t* bsm_ = smw + 2 * PJSTG;   // [2][128][32w]

    const int bn = blockIdx.x, bm = blockIdx.y;
    const int tid = threadIdx.x, lane = tid & 31, w = tid >> 5;
    const int wm = w >> 1, wn = w & 1;
    const int g = lane >> 2, t4 = lane & 3;
    const uint32_t a_sb = (uint32_t)__cvta_generic_to_shared(asm_);
    const uint32_t b_sb = (uint32_t)__cvta_generic_to_shared(bsm_);

    // prefetch stage 0
    #pragma unroll
    for (int j = 0; j < 4; j++) {
        int i = tid + j * 256;          // 1024 chunks each for A and B
        int row = i >> 3, c = i & 7;
        cpa16(a_sb + row * 128 + 16 * (c ^ (row & 7)),
              &g_Xh[(size_t)(bm * 128 + row) * 512 + c * 8]);
        cpa16(b_sb + row * 128 + 16 * (c ^ (row & 7)),
              &g_Wt[(size_t)(bn * 128 + row) * 512 + c * 8]);
    }
    cpa_commit();

    float acc[2][8][4] = {};

    for (int kt = 0; kt < 8; kt++) {
        const int buf = kt & 1;
        cpa_wait0();
        __syncthreads();
        if (kt + 1 < 8) {
            const int k0 = (kt + 1) * 64;
            const uint32_t ab = a_sb + (buf ^ 1) * (PJSTG * 4);
            const uint32_t bb = b_sb + (buf ^ 1) * (PJSTG * 4);
            #pragma unroll
            for (int j = 0; j < 4; j++) {
                int i = tid + j * 256;
                int row = i >> 3, c = i & 7;
                cpa16(ab + row * 128 + 16 * (c ^ (row & 7)),
                      &g_Xh[(size_t)(bm * 128 + row) * 512 + k0 + c * 8]);
                cpa16(bb + row * 128 + 16 * (c ^ (row & 7)),
                      &g_Wt[(size_t)(bn * 128 + row) * 512 + k0 + c * 8]);
            }
            cpa_commit();
        }
        const uint32_t* Ab = asm_ + buf * PJSTG;
        const uint32_t* Bb = bsm_ + buf * PJSTG;

        #pragma unroll
        for (int ks = 0; ks < 4; ks++) {
            uint32_t a[2][4];
            #pragma unroll
            for (int mt = 0; mt < 2; mt++) {
                int row = wm * 32 + mt * 16 + g;
                a[mt][0] = Ab[row * 32 + 4 * ((2 * ks) ^ g) + t4];
                a[mt][1] = Ab[(row + 8) * 32 + 4 * ((2 * ks) ^ g) + t4];
                a[mt][2] = Ab[row * 32 + 4 * ((2 * ks + 1) ^ g) + t4];
                a[mt][3] = Ab[(row + 8) * 32 + 4 * ((2 * ks + 1) ^ g) + t4];
            }
            #pragma unroll
            for (int nt = 0; nt < 8; nt++) {
                int col = wn * 64 + nt * 8 + g;
                uint32_t b0 = Bb[col * 32 + 4 * ((2 * ks) ^ g) + t4];
                uint32_t b1 = Bb[col * 32 + 4 * ((2 * ks + 1) ^ g) + t4];
                #pragma unroll
                for (int mt = 0; mt < 2; mt++)
                    mma16(acc[mt][nt], a[mt][0], a[mt][1], a[mt][2], a[mt][3], b0, b1);
            }
        }
    }

    // epilogue
    const int colg0 = bn * 128;
    const int sel = (colg0 < 1024) ? 0 : (colg0 < 2048) ? 1 : 2;
    const float qs = (sel == 0) ? 0.125f : 1.0f;
    #pragma unroll
    for (int mt = 0; mt < 2; mt++) {
        int row0 = bm * 128 + wm * 32 + mt * 16 + g;
        #pragma unroll
        for (int nt = 0; nt < 8; nt++) {
            int colg = colg0 + wn * 64 + nt * 8 + 2 * t4;
            float b0 = g_bias[colg], b1 = g_bias[colg + 1];
            float v00 = (acc[mt][nt][0] + b0) * qs, v01 = (acc[mt][nt][1] + b1) * qs;
            float v10 = (acc[mt][nt][2] + b0) * qs, v11 = (acc[mt][nt][3] + b1) * qs;
            if (sel < 2) {
                __half* dst = sel ? g_K : g_Q;
                int col = colg & 1023;
                *(uint32_t*)&dst[(size_t)row0 * 1024 + col]       = f2h2(v00, v01);
                *(uint32_t*)&dst[(size_t)(row0 + 8) * 1024 + col] = f2h2(v10, v11);
            } else {
                int cv = colg - 2048;
                int hh = cv >> 6, d = cv & 63;
                int bb2 = row0 >> 10, tok = row0 & 1023;
                size_t base = (size_t)(bb2 * 8 + hh) * 64;
                g_Vt[(base + d) * NN + tok]         = __float2half_rn(v00);
                g_Vt[(base + d + 1) * NN + tok]     = __float2half_rn(v01);
                g_Vt[(base + d) * NN + tok + 8]     = __float2half_rn(v10);
                g_Vt[(base + d + 1) * NN + tok + 8] = __float2half_rn(v11);
            }
        }
    }
}

// ----------------------------------------------------------------------------
// Differential attention (unchanged from round 5): fp16 mma, 512 threads,
// 128 q-rows/CTA, cp.async double-buffered K/V, P stays in registers.
// ----------------------------------------------------------------------------
#define KWORDS 4096
#define VWORDS 2048

__global__ __launch_bounds__(512, 1) void diff_attn(float* __restrict__ out) {
    extern __shared__ uint32_t smw[];
    uint32_t* ksm = smw;
    uint32_t* vsm = ksm + 2 * KWORDS;
    float*    osm = (float*)(vsm + 2 * VWORDS);
    uint32_t* qsm = (uint32_t*)osm;

    const int qt = blockIdx.x, h = blockIdx.y, b = blockIdx.z;
    const int tid = threadIdx.x, lane = tid & 31, w = tid >> 5;
    const int path = w >> 3, wp = w & 7;
    const int g = lane >> 2, t4 = lane & 3;
    const size_t qrow0 = (size_t)b * NN + (size_t)qt * 128;
    const size_t vhbase = (size_t)(b * 8 + h) * 64;

    {
        const size_t krow0 = (size_t)b * NN;
        #pragma unroll
        for (int j = 0; j < 2; j++) {
            int i = tid + j * 512;
            int key = i >> 4, c = i & 15;
            uint32_t ds = (uint32_t)__cvta_generic_to_shared(ksm) +
                          key * 256 + 16 * ((c & 8) | ((c & 7) ^ (key & 7)));
            cpa16(ds, &g_K[(krow0 + key) * TD + (size_t)h * 128 + c * 8]);
        }
        {
            int d = tid >> 3, c = tid & 7;
            uint32_t ds = (uint32_t)__cvta_generic_to_shared(vsm) +
                          d * 128 + 16 * (c ^ (d & 7));
            cpa16(ds, &g_Vt[(vhbase + d) * NN + c * 8]);
        }
        cpa_commit();
    }
    #pragma unroll
    for (int j = 0; j < 4; j++) {
        int i = tid + j * 512;
        int row = i >> 4, c = i & 15;
        uint32_t ds = (uint32_t)__cvta_generic_to_shared(qsm) +
                      row * 256 + 16 * ((c & 8) | ((c & 7) ^ (row & 7)));
        cpa16(ds, &g_Q[(qrow0 + row) * TD + (size_t)h * 128 + c * 8]);
    }
    cpa_commit();
    cpa_wait0();
    __syncthreads();

    uint32_t qa[4][4];
    {
        const int rq = wp * 16 + g;
        #pragma unroll
        for (int ks = 0; ks < 4; ks++) {
            int c0 = (path * 8) | ((2 * ks) ^ g);
            int c1 = (path * 8) | ((2 * ks + 1) ^ g);
            qa[ks][0] = qsm[rq * 64 + 4 * c0 + t4];
            qa[ks][1] = qsm[(rq + 8) * 64 + 4 * c0 + t4];
            qa[ks][2] = qsm[rq * 64 + 4 * c1 + t4];
            qa[ks][3] = qsm[(rq + 8) * 64 + 4 * c1 + t4];
        }
    }

    float acco[8][4] = {};
    float m0 = -1e30f, m1 = -1e30f, l0 = 0.f, l1 = 0.f;

    for (int kt = 0; kt < NN / 64; kt++) {
        const int buf = kt & 1;
        cpa_wait0();
        __syncthreads();

        if (kt + 1 < NN / 64) {
            const size_t krow0 = (size_t)b * NN + (size_t)(kt + 1) * 64;
            const int klocal = (kt + 1) * 64;
            uint32_t kb_s = (uint32_t)__cvta_generic_to_shared(ksm + (buf ^ 1) * KWORDS);
            uint32_t vb_s = (uint32_t)__cvta_generic_to_shared(vsm + (buf ^ 1) * VWORDS);
            #pragma unroll
            for (int j = 0; j < 2; j++) {
                int i = tid + j * 512;
                int key = i >> 4, c = i & 15;
                uint32_t ds = kb_s + key * 256 + 16 * ((c & 8) | ((c & 7) ^ (key & 7)));
                cpa16(ds, &g_K[(krow0 + key) * TD + (size_t)h * 128 + c * 8]);
            }
            {
                int d = tid >> 3, c = tid & 7;
                uint32_t ds = vb_s + d * 128 + 16 * (c ^ (d & 7));
                cpa16(ds, &g_Vt[(vhbase + d) * NN + klocal + c * 8]);
            }
            cpa_commit();
        }

        const uint32_t* Kb = ksm + buf * KWORDS;
        const uint32_t* Vb = vsm + buf * VWORDS;

        float accs[8][4] = {};
        #pragma unroll
        for (int ks = 0; ks < 4; ks++) {
            #pragma unroll
            for (int nt = 0; nt < 8; nt++) {
                const int key = nt * 8 + g;
                uint32_t b0 = Kb[key * 64 + 4 * ((path * 8) | ((2 * ks) ^ g)) + t4];
                uint32_t b1 = Kb[key * 64 + 4 * ((path * 8) | ((2 * ks + 1) ^ g)) + t4];
                mma16(accs[nt], qa[ks][0], qa[ks][1], qa[ks][2], qa[ks][3], b0, b1);
            }
        }

        float tm0 = -1e30f, tm1 = -1e30f;
        #pragma unroll
        for (int nt = 0; nt < 8; nt++) {
            tm0 = fmaxf(tm0, fmaxf(accs[nt][0], accs[nt][1]));
            tm1 = fmaxf(tm1, fmaxf(accs[nt][2], accs[nt][3]));
        }
        tm0 = fmaxf(tm0, __shfl_xor_sync(0xffffffffu, tm0, 1));
        tm0 = fmaxf(tm0, __shfl_xor_sync(0xffffffffu, tm0, 2));
        tm1 = fmaxf(tm1, __shfl_xor_sync(0xffffffffu, tm1, 1));
        tm1 = fmaxf(tm1, __shfl_xor_sync(0xffffffffu, tm1, 2));
        const float mn0 = fmaxf(m0, tm0), mn1 = fmaxf(m1, tm1);
        const float al0 = __expf(m0 - mn0), al1 = __expf(m1 - mn1);
        float s0 = 0.f, s1 = 0.f;
        #pragma unroll
        for (int nt = 0; nt < 8; nt++) {
            accs[nt][0] = __expf(accs[nt][0] - mn0);
            accs[nt][1] = __expf(accs[nt][1] - mn0);
            accs[nt][2] = __expf(accs[nt][2] - mn1);
            accs[nt][3] = __expf(accs[nt][3] - mn1);
            s0 += accs[nt][0] + accs[nt][1];
            s1 += accs[nt][2] + accs[nt][3];
        }
        s0 += __shfl_xor_sync(0xffffffffu, s0, 1);
        s0 += __shfl_xor_sync(0xffffffffu, s0, 2);
        s1 += __shfl_xor_sync(0xffffffffu, s1, 1);
        s1 += __shfl_xor_sync(0xffffffffu, s1, 2);
        l0 = l0 * al0 + s0;  m0 = mn0;
        l1 = l1 * al1 + s1;  m1 = mn1;

        #pragma unroll
        for (int nt = 0; nt < 8; nt++) {
            acco[nt][0] *= al0;  acco[nt][1] *= al0;
            acco[nt][2] *= al1;  acco[nt][3] *= al1;
        }
        #pragma unroll
        for (int ks = 0; ks < 4; ks++) {
            uint32_t a0 = f2h2(accs[2 * ks][0],     accs[2 * ks][1]);
            uint32_t a1 = f2h2(accs[2 * ks][2],     accs[2 * ks][3]);
            uint32_t a2 = f2h2(accs[2 * ks + 1][0], accs[2 * ks + 1][1]);
            uint32_t a3 = f2h2(accs[2 * ks + 1][2], accs[2 * ks + 1][3]);
            #pragma unroll
            for (int nt = 0; nt < 8; nt++) {
                const int d = nt * 8 + g;
                uint32_t b0 = Vb[d * 32 + 4 * ((2 * ks) ^ g) + t4];
                uint32_t b1 = Vb[d * 32 + 4 * ((2 * ks + 1) ^ g) + t4];
                mma16(acco[nt], a0, a1, a2, a3, b0, b1);
            }
        }
    }

    if (path == 1) {
        const float inv0 = 0.5f / l0, inv1 = 0.5f / l1;
        const int row = wp * 16 + g;
        #pragma unroll
        for (int nt = 0; nt < 8; nt++) {
            const int col = nt * 8 + 2 * t4;
            *(float2*)&osm[row * 68 + col]       = make_float2(acco[nt][0] * inv0, acco[nt][1] * inv0);
            *(float2*)&osm[(row + 8) * 68 + col] = make_float2(acco[nt][2] * inv1, acco[nt][3] * inv1);
        }
    }
    __syncthreads();
    if (path == 0) {
        const float inv0 = 1.0f / l0, inv1 = 1.0f / l1;
        const int row = wp * 16 + g;
        #pragma unroll
        for (int nt = 0; nt < 8; nt++) {
            const int col = nt * 8 + 2 * t4;
            float2 o0 = *(float2*)&osm[row * 68 + col];
            float2 o1 = *(float2*)&osm[(row + 8) * 68 + col];
            float2 r0 = make_float2(acco[nt][0] * inv0 - o0.x, acco[nt][1] * inv0 - o0.y);
            float2 r1 = make_float2(acco[nt][2] * inv1 - o1.x, acco[nt][3] * inv1 - o1.y);
            *(float2*)&out[(qrow0 + row) * DD + (size_t)h * 64 + col]     = r0;
            *(float2*)&out[(qrow0 + row + 8) * DD + (size_t)h * 64 + col] = r1;
        }
    }
}

static const size_t ATTN_SMEM = (2 * KWORDS + 2 * VWORDS + 128 * 68) * 4;  // 83968 B
static const size_t PROJ_SMEM = 4 * PJSTG * 4;                              // 65536 B

extern "C" void kernel_launch(void* const* d_in, const int* in_sizes, int n_in,
                              void* d_out, int out_size) {
    (void)in_sizes; (void)n_in; (void)out_size;
    const float* x  = (const float*)d_in[0];
    const float* Wq = (const float*)d_in[1];
    const float* bq = (const float*)d_in[2];
    const float* Wk = (const float*)d_in[3];
    const float* bk = (const float*)d_in[4];
    const float* Wv = (const float*)d_in[5];
    const float* bv = (const float*)d_in[6];
    float* out = (float*)d_out;

    cudaFuncSetAttribute(diff_attn, cudaFuncAttributeMaxDynamicSharedMemorySize,
                         (int)ATTN_SMEM);
    cudaFuncSetAttribute(proj_mma, cudaFuncAttributeMaxDynamicSharedMemorySize,
                         (int)PROJ_SMEM);

    convert_all<<<2314, 256>>>(x, Wq, bq, Wk, bk, Wv, bv);
    proj_mma<<<dim3(NTOT / 128, MROWS / 128), 256, PROJ_SMEM>>>();
    diff_attn<<<dim3(NN / 128, HH, BB), 512, ATTN_SMEM>>>(out);
}

// round 7
// speedup vs baseline: 11.3431x; 1.1201x over previous
#include <cuda_runtime.h>
#include <cuda_fp16.h>
#include <cstdint>

#define BB 4
#define NN 1024
#define DD 512
#define HH 8
#define TD 1024            // Q/K projected width
#define MROWS (BB*NN)      // 4096
#define NTOT 2560          // combined output columns: Q 1024 | K 1024 | V 512

// fp16 staging
__device__ __half g_Xh[(size_t)MROWS * 512];
__device__ __half g_Wt[(size_t)NTOT * 512];     // [n][k] (transposed weights)
__device__ float  g_bias[NTOT];
// Projected activations
__device__ __half g_Q[(size_t)MROWS * TD];
__device__ __half g_K[(size_t)MROWS * TD];
__device__ __half g_Vt[(size_t)BB * HH * 64 * NN];   // [b*8+h][d][token]

__device__ __forceinline__ uint32_t f2h2(float lo, float hi) {
    uint32_t r;
    asm("cvt.rn.f16x2.f32 %0, %1, %2;" : "=r"(r) : "f"(hi), "f"(lo));
    return r;
}
__device__ __forceinline__ uint32_t h2ex2(uint32_t x) {
    uint32_t r;
    asm("ex2.approx.f16x2 %0, %1;" : "=r"(r) : "r"(x));
    return r;
}

__device__ __forceinline__ void mma16(float* c, uint32_t a0, uint32_t a1,
                                      uint32_t a2, uint32_t a3,
                                      uint32_t b0, uint32_t b1) {
    asm volatile(
        "mma.sync.aligned.m16n8k16.row.col.f32.f16.f16.f32 "
        "{%0,%1,%2,%3},{%4,%5,%6,%7},{%8,%9},{%0,%1,%2,%3};"
        : "+f"(c[0]), "+f"(c[1]), "+f"(c[2]), "+f"(c[3])
        : "r"(a0), "r"(a1), "r"(a2), "r"(a3), "r"(b0), "r"(b1));
}

__device__ __forceinline__ void ldsm4(uint32_t& r0, uint32_t& r1,
                                      uint32_t& r2, uint32_t& r3, uint32_t addr) {
    asm volatile("ldmatrix.sync.aligned.m8n8.x4.shared.b16 {%0,%1,%2,%3}, [%4];"
                 : "=r"(r0), "=r"(r1), "=r"(r2), "=r"(r3) : "r"(addr));
}

__device__ __forceinline__ void cpa16(uint32_t saddr, const void* gptr) {
    asm volatile("cp.async.cg.shared.global [%0], [%1], 16;" :: "r"(saddr), "l"(gptr));
}
__device__ __forceinline__ void cpa_commit() { asm volatile("cp.async.commit_group;"); }
__device__ __forceinline__ void cpa_wait0()  { asm volatile("cp.async.wait_group 0;"); }

// ----------------------------------------------------------------------------
// Convert: x -> g_Xh; Wq/Wk/Wv -> g_Wt (transposed, fp16); biases -> g_bias.
// ----------------------------------------------------------------------------
__global__ __launch_bounds__(256) void convert_all(
    const float* __restrict__ x,
    const float* __restrict__ Wq, const float* __restrict__ bq,
    const float* __restrict__ Wk, const float* __restrict__ bk,
    const float* __restrict__ Wv, const float* __restrict__ bv) {
    const int bx = blockIdx.x, tid = threadIdx.x;
    if (bx < 1024) {
        int base = bx * 2048 + tid * 8;
        float4 v0 = *(const float4*)&x[base];
        float4 v1 = *(const float4*)&x[base + 4];
        uint4 o;
        o.x = f2h2(v0.x, v0.y);  o.y = f2h2(v0.z, v0.w);
        o.z = f2h2(v1.x, v1.y);  o.w = f2h2(v1.z, v1.w);
        *(uint4*)&g_Xh[base] = o;
    } else if (bx < 1024 + 1280) {
        __shared__ __half ts[32][33];
        int t = bx - 1024;
        const float* W; int N, kt, nt, nrow0;
        if (t < 512)      { W = Wq; N = 1024; kt = t >> 5;          nt = t & 31;          nrow0 = 0;    }
        else if (t < 1024){ W = Wk; N = 1024; kt = (t - 512) >> 5;  nt = (t - 512) & 31;  nrow0 = 1024; }
        else              { W = Wv; N = 512;  kt = (t - 1024) >> 4; nt = (t - 1024) & 15; nrow0 = 2048; }
        #pragma unroll
        for (int p = 0; p < 4; p++) {
            int r = p * 8 + (tid >> 5), c = tid & 31;
            ts[r][c] = __float2half_rn(W[(size_t)(kt * 32 + r) * N + nt * 32 + c]);
        }
        __syncthreads();
        #pragma unroll
        for (int p = 0; p < 4; p++) {
            int n = p * 8 + (tid >> 5), k = tid & 31;
            g_Wt[(size_t)(nrow0 + nt * 32 + n) * 512 + kt * 32 + k] = ts[k][n];
        }
    } else {
        int i = (bx - 2304) * 256 + tid;
        if (i < NTOT)
            g_bias[i] = (i < 1024) ? bq[i] : (i < 2048) ? bk[i - 1024] : bv[i - 2048];
    }
}

// ----------------------------------------------------------------------------
// Pipelined fp16 projection GEMM: C[4096, 2560] = g_Xh @ g_Wt^T (+bias).
// ----------------------------------------------------------------------------
#define PJSTG 4096

__global__ __launch_bounds__(256) void proj_mma(void) {
    extern __shared__ uint32_t smw[];
    uint32_t* asm_ = smw;
    uint32_t* bsm_ = smw + 2 * PJSTG;

    const int bn = blockIdx.x, bm = blockIdx.y;
    const int tid = threadIdx.x, lane = tid & 31, w = tid >> 5;
    const int wm = w >> 1, wn = w & 1;
    const int g = lane >> 2, t4 = lane & 3;
    const uint32_t a_sb = (uint32_t)__cvta_generic_to_shared(asm_);
    const uint32_t b_sb = (uint32_t)__cvta_generic_to_shared(bsm_);

    #pragma unroll
    for (int j = 0; j < 4; j++) {
        int i = tid + j * 256;
        int row = i >> 3, c = i & 7;
        cpa16(a_sb + row * 128 + 16 * (c ^ (row & 7)),
              &g_Xh[(size_t)(bm * 128 + row) * 512 + c * 8]);
        cpa16(b_sb + row * 128 + 16 * (c ^ (row & 7)),
              &g_Wt[(size_t)(bn * 128 + row) * 512 + c * 8]);
    }
    cpa_commit();

    float acc[2][8][4] = {};

    for (int kt = 0; kt < 8; kt++) {
        const int buf = kt & 1;
        cpa_wait0();
        __syncthreads();
        if (kt + 1 < 8) {
            const int k0 = (kt + 1) * 64;
            const uint32_t ab = a_sb + (buf ^ 1) * (PJSTG * 4);
            const uint32_t bb = b_sb + (buf ^ 1) * (PJSTG * 4);
            #pragma unroll
            for (int j = 0; j < 4; j++) {
                int i = tid + j * 256;
                int row = i >> 3, c = i & 7;
                cpa16(ab + row * 128 + 16 * (c ^ (row & 7)),
                      &g_Xh[(size_t)(bm * 128 + row) * 512 + k0 + c * 8]);
                cpa16(bb + row * 128 + 16 * (c ^ (row & 7)),
                      &g_Wt[(size_t)(bn * 128 + row) * 512 + k0 + c * 8]);
            }
            cpa_commit();
        }
        const uint32_t* Ab = asm_ + buf * PJSTG;
        const uint32_t* Bb = bsm_ + buf * PJSTG;

        #pragma unroll
        for (int ks = 0; ks < 4; ks++) {
            uint32_t a[2][4];
            #pragma unroll
            for (int mt = 0; mt < 2; mt++) {
                int row = wm * 32 + mt * 16 + g;
                a[mt][0] = Ab[row * 32 + 4 * ((2 * ks) ^ g) + t4];
                a[mt][1] = Ab[(row + 8) * 32 + 4 * ((2 * ks) ^ g) + t4];
                a[mt][2] = Ab[row * 32 + 4 * ((2 * ks + 1) ^ g) + t4];
                a[mt][3] = Ab[(row + 8) * 32 + 4 * ((2 * ks + 1) ^ g) + t4];
            }
            #pragma unroll
            for (int nt = 0; nt < 8; nt++) {
                int col = wn * 64 + nt * 8 + g;
                uint32_t b0 = Bb[col * 32 + 4 * ((2 * ks) ^ g) + t4];
                uint32_t b1 = Bb[col * 32 + 4 * ((2 * ks + 1) ^ g) + t4];
                #pragma unroll
                for (int mt = 0; mt < 2; mt++)
                    mma16(acc[mt][nt], a[mt][0], a[mt][1], a[mt][2], a[mt][3], b0, b1);
            }
        }
    }

    const int colg0 = bn * 128;
    const int sel = (colg0 < 1024) ? 0 : (colg0 < 2048) ? 1 : 2;
    const float qs = (sel == 0) ? 0.125f : 1.0f;
    #pragma unroll
    for (int mt = 0; mt < 2; mt++) {
        int row0 = bm * 128 + wm * 32 + mt * 16 + g;
        #pragma unroll
        for (int nt = 0; nt < 8; nt++) {
            int colg = colg0 + wn * 64 + nt * 8 + 2 * t4;
            float b0 = g_bias[colg], b1 = g_bias[colg + 1];
            float v00 = (acc[mt][nt][0] + b0) * qs, v01 = (acc[mt][nt][1] + b1) * qs;
            float v10 = (acc[mt][nt][2] + b0) * qs, v11 = (acc[mt][nt][3] + b1) * qs;
            if (sel < 2) {
                __half* dst = sel ? g_K : g_Q;
                int col = colg & 1023;
                *(uint32_t*)&dst[(size_t)row0 * 1024 + col]       = f2h2(v00, v01);
                *(uint32_t*)&dst[(size_t)(row0 + 8) * 1024 + col] = f2h2(v10, v11);
            } else {
                int cv = colg - 2048;
                int hh = cv >> 6, d = cv & 63;
                int bb2 = row0 >> 10, tok = row0 & 1023;
                size_t base = (size_t)(bb2 * 8 + hh) * 64;
                g_Vt[(base + d) * NN + tok]         = __float2half_rn(v00);
                g_Vt[(base + d + 1) * NN + tok]     = __float2half_rn(v01);
                g_Vt[(base + d) * NN + tok + 8]     = __float2half_rn(v10);
                g_Vt[(base + d + 1) * NN + tok + 8] = __float2half_rn(v11);
            }
        }
    }
}

// ----------------------------------------------------------------------------
// Differential attention: fp16 mma, ldmatrix B-frags, f16x2 exp, l via
// ones-column mma. 512 threads, 128 q-rows/CTA, double-buffered K/V.
// ----------------------------------------------------------------------------
#define KWORDS 4096
#define VWORDS 2048
#define ONES16 0x3C003C00u

__global__ __launch_bounds__(512, 1) void diff_attn(float* __restrict__ out) {
    extern __shared__ uint32_t smw[];
    uint32_t* ksm = smw;
    uint32_t* vsm = ksm + 2 * KWORDS;
    float*    osm = (float*)(vsm + 2 * VWORDS);
    uint32_t* qsm = (uint32_t*)osm;

    const int qt = blockIdx.x, h = blockIdx.y, b = blockIdx.z;
    const int tid = threadIdx.x, lane = tid & 31, w = tid >> 5;
    const int path = w >> 3, wp = w & 7;
    const int g = lane >> 2, t4 = lane & 3;
    const int quad = lane >> 3, r8 = lane & 7, q0 = quad & 1, hi = quad >> 1;
    const size_t qrow0 = (size_t)b * NN + (size_t)qt * 128;
    const size_t vhbase = (size_t)(b * 8 + h) * 64;

    // ---- prefetch K/V tile 0 ----
    {
        const size_t krow0 = (size_t)b * NN;
        #pragma unroll
        for (int j = 0; j < 2; j++) {
            int i = tid + j * 512;
            int key = i >> 4, c = i & 15;
            uint32_t ds = (uint32_t)__cvta_generic_to_shared(ksm) +
                          key * 256 + 16 * ((c & 8) | ((c & 7) ^ (key & 7)));
            cpa16(ds, &g_K[(krow0 + key) * TD + (size_t)h * 128 + c * 8]);
        }
        {
            int d = tid >> 3, c = tid & 7;
            uint32_t ds = (uint32_t)__cvta_generic_to_shared(vsm) +
                          d * 128 + 16 * (c ^ (d & 7));
            cpa16(ds, &g_Vt[(vhbase + d) * NN + c * 8]);
        }
        cpa_commit();
    }
    // ---- stage Q ----
    #pragma unroll
    for (int j = 0; j < 4; j++) {
        int i = tid + j * 512;
        int row = i >> 4, c = i & 15;
        uint32_t ds = (uint32_t)__cvta_generic_to_shared(qsm) +
                      row * 256 + 16 * ((c & 8) | ((c & 7) ^ (row & 7)));
        cpa16(ds, &g_Q[(qrow0 + row) * TD + (size_t)h * 128 + c * 8]);
    }
    cpa_commit();
    cpa_wait0();
    __syncthreads();

    // ---- lift Q to A-fragments ----
    uint32_t qa[4][4];
    {
        const int rq = wp * 16 + g;
        #pragma unroll
        for (int ks = 0; ks < 4; ks++) {
            int cA = (path * 8) | ((2 * ks) ^ g);
            int cB = (path * 8) | ((2 * ks + 1) ^ g);
            qa[ks][0] = qsm[rq * 64 + 4 * cA + t4];
            qa[ks][1] = qsm[(rq + 8) * 64 + 4 * cA + t4];
            qa[ks][2] = qsm[rq * 64 + 4 * cB + t4];
            qa[ks][3] = qsm[(rq + 8) * 64 + 4 * cB + t4];
        }
    }

    const uint32_t ks_base = (uint32_t)__cvta_generic_to_shared(ksm);
    const uint32_t vs_base = (uint32_t)__cvta_generic_to_shared(vsm);
    const uint32_t krow_off = (uint32_t)((hi * 8 + r8) * 256 + path * 128);
    const uint32_t vrow_off = (uint32_t)((hi * 8 + r8) * 128);

    float acco[8][4] = {};
    float accl[4] = {};
    float m0 = -1e30f, m1 = -1e30f;

    for (int kt = 0; kt < NN / 64; kt++) {
        const int buf = kt & 1;
        cpa_wait0();
        __syncthreads();

        if (kt + 1 < NN / 64) {
            const size_t krow0 = (size_t)b * NN + (size_t)(kt + 1) * 64;
            const int klocal = (kt + 1) * 64;
            uint32_t kb_s = ks_base + (buf ^ 1) * (KWORDS * 4);
            uint32_t vb_s = vs_base + (buf ^ 1) * (VWORDS * 4);
            #pragma unroll
            for (int j = 0; j < 2; j++) {
                int i = tid + j * 512;
                int key = i >> 4, c = i & 15;
                uint32_t ds = kb_s + key * 256 + 16 * ((c & 8) | ((c & 7) ^ (key & 7)));
                cpa16(ds, &g_K[(krow0 + key) * TD + (size_t)h * 128 + c * 8]);
            }
            {
                int d = tid >> 3, c = tid & 7;
                uint32_t ds = vb_s + d * 128 + 16 * (c ^ (d & 7));
                cpa16(ds, &g_Vt[(vhbase + d) * NN + klocal + c * 8]);
            }
            cpa_commit();
        }

        const uint32_t kls = ks_base + buf * (KWORDS * 4) + krow_off;
        const uint32_t vls = vs_base + buf * (VWORDS * 4) + vrow_off;

        // ---- S = Q @ K^T via ldmatrix B-frags ----
        float accs[8][4] = {};
        #pragma unroll
        for (int ks = 0; ks < 4; ks++) {
            const uint32_t sw = 16u * (uint32_t)((2 * ks + q0) ^ r8);
            #pragma unroll
            for (int p = 0; p < 4; p++) {
                uint32_t b0, b1, b2, b3;
                ldsm4(b0, b1, b2, b3, kls + p * 4096 + sw);
                mma16(accs[2 * p],     qa[ks][0], qa[ks][1], qa[ks][2], qa[ks][3], b0, b1);
                mma16(accs[2 * p + 1], qa[ks][0], qa[ks][1], qa[ks][2], qa[ks][3], b2, b3);
            }
        }

        // ---- online softmax: f32 max, f16x2 exp ----
        float tm0 = -1e30f, tm1 = -1e30f;
        #pragma unroll
        for (int nt = 0; nt < 8; nt++) {
            tm0 = fmaxf(tm0, fmaxf(accs[nt][0], accs[nt][1]));
            tm1 = fmaxf(tm1, fmaxf(accs[nt][2], accs[nt][3]));
        }
        tm0 = fmaxf(tm0, __shfl_xor_sync(0xffffffffu, tm0, 1));
        tm0 = fmaxf(tm0, __shfl_xor_sync(0xffffffffu, tm0, 2));
        tm1 = fmaxf(tm1, __shfl_xor_sync(0xffffffffu, tm1, 1));
        tm1 = fmaxf(tm1, __shfl_xor_sync(0xffffffffu, tm1, 2));
        const float mn0 = fmaxf(m0, tm0), mn1 = fmaxf(m1, tm1);
        const float al0 = __expf(m0 - mn0), al1 = __expf(m1 - mn1);
        const float L2E = 1.442695041f;
        const float e0 = -mn0 * L2E, e1 = -mn1 * L2E;

        uint32_t pl[8], ph[8];
        #pragma unroll
        for (int nt = 0; nt < 8; nt++) {
            pl[nt] = h2ex2(f2h2(fmaf(accs[nt][0], L2E, e0), fmaf(accs[nt][1], L2E, e0)));
            ph[nt] = h2ex2(f2h2(fmaf(accs[nt][2], L2E, e1), fmaf(accs[nt][3], L2E, e1)));
        }
        m0 = mn0;  m1 = mn1;

        // ---- rescale accumulators (incl. l-column) ----
        #pragma unroll
        for (int nt = 0; nt < 8; nt++) {
            acco[nt][0] *= al0;  acco[nt][1] *= al0;
            acco[nt][2] *= al1;  acco[nt][3] *= al1;
        }
        accl[0] *= al0;  accl[1] *= al0;  accl[2] *= al1;  accl[3] *= al1;

        // ---- acco += P @ V; l-column via ones-B mma ----
        #pragma unroll
        for (int ks = 0; ks < 4; ks++) {
            const uint32_t sw = 16u * (uint32_t)((2 * ks + q0) ^ r8);
            const uint32_t a0 = pl[2 * ks], a1 = ph[2 * ks];
            const uint32_t a2 = pl[2 * ks + 1], a3 = ph[2 * ks + 1];
            mma16(accl, a0, a1, a2, a3, ONES16, ONES16);
            #pragma unroll
            for (int p = 0; p < 4; p++) {
                uint32_t b0, b1, b2, b3;
                ldsm4(b0, b1, b2, b3, vls + p * 2048 + sw);
                mma16(acco[2 * p],     a0, a1, a2, a3, b0, b1);
                mma16(acco[2 * p + 1], a0, a1, a2, a3, b2, b3);
            }
        }
    }

    // ---- combine ----
    const float l0 = accl[0], l1 = accl[2];
    if (path == 1) {
        const float inv0 = 0.5f / l0, inv1 = 0.5f / l1;
        const int row = wp * 16 + g;
        #pragma unroll
        for (int nt = 0; nt < 8; nt++) {
            const int col = nt * 8 + 2 * t4;
            *(float2*)&osm[row * 68 + col]       = make_float2(acco[nt][0] * inv0, acco[nt][1] * inv0);
            *(float2*)&osm[(row + 8) * 68 + col] = make_float2(acco[nt][2] * inv1, acco[nt][3] * inv1);
        }
    }
    __syncthreads();
    if (path == 0) {
        const float inv0 = 1.0f / l0, inv1 = 1.0f / l1;
        const int row = wp * 16 + g;
        #pragma unroll
        for (int nt = 0; nt < 8; nt++) {
            const int col = nt * 8 + 2 * t4;
            float2 o0 = *(float2*)&osm[row * 68 + col];
            float2 o1 = *(float2*)&osm[(row + 8) * 68 + col];
            float2 r0 = make_float2(acco[nt][0] * inv0 - o0.x, acco[nt][1] * inv0 - o0.y);
            float2 r1 = make_float2(acco[nt][2] * inv1 - o1.x, acco[nt][3] * inv1 - o1.y);
            *(float2*)&out[(qrow0 + row) * DD + (size_t)h * 64 + col]     = r0;
            *(float2*)&out[(qrow0 + row + 8) * DD + (size_t)h * 64 + col] = r1;
        }
    }
}

static const size_t ATTN_SMEM = (2 * KWORDS + 2 * VWORDS + 128 * 68) * 4;  // 83968 B
static const size_t PROJ_SMEM = 4 * PJSTG * 4;                              // 65536 B

extern "C" void kernel_launch(void* const* d_in, const int* in_sizes, int n_in,
                              void* d_out, int out_size) {
    (void)in_sizes; (void)n_in; (void)out_size;
    const float* x  = (const float*)d_in[0];
    const float* Wq = (const float*)d_in[1];
    const float* bq = (const float*)d_in[2];
    const float* Wk = (const float*)d_in[3];
    const float* bk = (const float*)d_in[4];
    const float* Wv = (const float*)d_in[5];
    const float* bv = (const float*)d_in[6];
    float* out = (float*)d_out;

    cudaFuncSetAttribute(diff_attn, cudaFuncAttributeMaxDynamicSharedMemorySize,
                         (int)ATTN_SMEM);
    cudaFuncSetAttribute(proj_mma, cudaFuncAttributeMaxDynamicSharedMemorySize,
                         (int)PROJ_SMEM);

    convert_all<<<2314, 256>>>(x, Wq, bq, Wk, bk, Wv, bv);
    proj_mma<<<dim3(NTOT / 128, MROWS / 128), 256, PROJ_SMEM>>>();
    diff_attn<<<dim3(NN / 128, HH, BB), 512, ATTN_SMEM>>>(out);
}